// round 5
// baseline (speedup 1.0000x reference)
#include <cuda_runtime.h>
#include <cstdint>

#define NN     16000
#define IN_DIM 128
#define HID    64
#define BB     32
#define PP     128
#define DD     100
#define NCLS   10
#define INV_PI 0.31830988618379067f

// ---------------- scratch (device globals; no allocation allowed) -----------
__device__ float g_filt[NN];                       // node filtration values
__device__ float g_imgs[BB * 2 * DD * DD];         // normalized pers images [B,2,D,D]
__device__ float g_y1[BB * 16 * 50 * 50];          // conv1 pooled out
__device__ float g_y2[BB * 32 * 25 * 25];          // conv2 pooled out

// ======================= K1: node filtration MLP ============================
__global__ __launch_bounds__(256) void filt_kernel(
    const float* __restrict__ x, const float* __restrict__ w1,
    const float* __restrict__ b1, const float* __restrict__ w2,
    const float* __restrict__ b2, float* __restrict__ out_filt)
{
    const int tid   = threadIdx.x;
    const int j     = tid & 63;
    const int chunk = tid >> 6;

    float wr[32];
    #pragma unroll
    for (int k = 0; k < 32; ++k)
        wr[k] = w1[(chunk * 32 + k) * HID + j];
    const float b1j = b1[j];
    const float w2j = w2[j];
    const float b2v = b2[0];

    __shared__ float xs[4][IN_DIM];
    __shared__ float part[4][4 * 64];
    __shared__ float nsum[4][2];

    for (int grp = 0; grp < 16; ++grp) {
        const int nbase = blockIdx.x * 64 + grp * 4;
        __syncthreads();
        for (int idx = tid; idx < 4 * IN_DIM; idx += 256) {
            int n = idx >> 7, c = idx & 127;
            xs[n][c] = x[(nbase + n) * IN_DIM + c];
        }
        __syncthreads();

        #pragma unroll
        for (int n = 0; n < 4; ++n) {
            const float4* xp = reinterpret_cast<const float4*>(xs[n] + chunk * 32);
            float s = 0.f;
            #pragma unroll
            for (int q = 0; q < 8; ++q) {
                float4 v = xp[q];
                s += v.x * wr[4 * q] + v.y * wr[4 * q + 1]
                   + v.z * wr[4 * q + 2] + v.w * wr[4 * q + 3];
            }
            part[n][chunk * 64 + j] = s;
        }
        __syncthreads();

        {
            const int n2 = chunk;
            float v = part[n2][j] + part[n2][64 + j]
                    + part[n2][128 + j] + part[n2][192 + j] + b1j;
            float h = fmaxf(v, 0.f) * w2j;
            #pragma unroll
            for (int off = 16; off; off >>= 1)
                h += __shfl_down_sync(0xffffffffu, h, off);
            if ((j & 31) == 0) nsum[n2][j >> 5] = h;
        }
        __syncthreads();
        if (tid < 4) {
            const int node = nbase + tid;
            float t = nsum[tid][0] + nsum[tid][1] + b2v;
            float f = 1.f / (1.f + __expf(-t));
            g_filt[node]   = f;
            out_filt[node] = f;
        }
    }
}

// ================ K2: persistence image (gather + exp + GEMM + norm) ========
#define PERS_SMEM_FLOATS (2 * PP * DD + PP + PP + 32)
__global__ __launch_bounds__(256) void pers_image_kernel(
    const int* __restrict__ pidx0, const int* __restrict__ pidx1)
{
    extern __shared__ float sm[];
    float* Us = sm;
    float* Vs = Us + PP * DD;
    float* bs = Vs + PP * DD;
    float* ps = bs + PP;
    float* red = ps + PP;

    const int m  = blockIdx.x;
    const int b  = m >> 1;
    const int ch = m & 1;
    const int* pidx = ch ? pidx1 : pidx0;
    const int tid = threadIdx.x;

    if (tid < PP) {
        int i0 = pidx[(b * PP + tid) * 2 + 0];
        int i1 = pidx[(b * PP + tid) * 2 + 1];
        float birth = g_filt[i0];
        bs[tid] = birth;
        ps[tid] = g_filt[i1] - birth;
    }
    __syncthreads();

    for (int idx = tid; idx < PP * DD; idx += 256) {
        int p = idx / DD, t = idx % DD;
        float c  = (float)t * 0.01f;
        float db = bs[p] - c;
        float dp = ps[p] - c;
        Us[idx] = __expf(-db * db);
        Vs[idx] = INV_PI * __expf(-dp * dp);
    }
    __syncthreads();

    float tv[48];
    float mx = 0.f;
    #pragma unroll
    for (int it = 0; it < 3; ++it) {
        const int tile = tid + it * 256;
        if (tile < 625) {
            const int i0 = (tile / 25) * 4;
            const int j0 = (tile % 25) * 4;
            float acc[16];
            #pragma unroll
            for (int k = 0; k < 16; ++k) acc[k] = 0.f;
            #pragma unroll 4
            for (int p = 0; p < PP; ++p) {
                float4 u = *reinterpret_cast<const float4*>(Us + p * DD + i0);
                float4 v = *reinterpret_cast<const float4*>(Vs + p * DD + j0);
                acc[0]  += u.x * v.x; acc[1]  += u.x * v.y; acc[2]  += u.x * v.z; acc[3]  += u.x * v.w;
                acc[4]  += u.y * v.x; acc[5]  += u.y * v.y; acc[6]  += u.y * v.z; acc[7]  += u.y * v.w;
                acc[8]  += u.z * v.x; acc[9]  += u.z * v.y; acc[10] += u.z * v.z; acc[11] += u.z * v.w;
                acc[12] += u.w * v.x; acc[13] += u.w * v.y; acc[14] += u.w * v.z; acc[15] += u.w * v.w;
            }
            #pragma unroll
            for (int k = 0; k < 16; ++k) {
                tv[it * 16 + k] = acc[k];
                mx = fmaxf(mx, acc[k]);
            }
        }
    }
    #pragma unroll
    for (int off = 16; off; off >>= 1)
        mx = fmaxf(mx, __shfl_down_sync(0xffffffffu, mx, off));
    if ((tid & 31) == 0) red[tid >> 5] = mx;
    __syncthreads();
    if (tid == 0) {
        float t = red[0];
        #pragma unroll
        for (int w = 1; w < 8; ++w) t = fmaxf(t, red[w]);
        red[0] = t;
    }
    __syncthreads();
    const float inv = 1.f / red[0];

    float* outp = g_imgs + m * (DD * DD);
    #pragma unroll
    for (int it = 0; it < 3; ++it) {
        const int tile = tid + it * 256;
        if (tile < 625) {
            const int i0 = (tile / 25) * 4;
            const int j0 = (tile % 25) * 4;
            #pragma unroll
            for (int a = 0; a < 4; ++a)
                #pragma unroll
                for (int c = 0; c < 4; ++c)
                    outp[(i0 + a) * DD + (j0 + c)] = tv[it * 16 + a * 4 + c] * inv;
        }
    }
}

// ============= K3/K4: fused conv(5x5, pad2) + ReLU + maxpool(2x2) ===========
// SPT=2: each thread computes TWO horizontally-adjacent pooled outputs (a 2x4
// conv strip) for OPT=4 output channels. Per ic: 12 patch LDS.128 + 28 weight
// LDS.128 vs 800 FFMA -> ~94% FMA issue mix.
// One position per thread (no pos loop). SEL: 0 = imgs->y1, 1 = y1->y2.
template<int IC, int W, int OC_BLOCK, int PR, int SEL>
__global__ __launch_bounds__(224, 2) void conv_pool_kernel(
    const float* __restrict__ wts, const float* __restrict__ bias)
{
    constexpr int OPT   = 4;
    constexpr int TR    = 2 * PR + 4;         // tile rows incl. halo
    constexpr int PC    = W / 2;              // pooled cols/rows
    constexpr int NPAIR = (PC + 1) / 2;       // pooled col pairs per row
    constexpr int WPMIN = 4 * NPAIR + 4;      // width needed by float4 strips
    constexpr int WP    = (W + 4 > WPMIN) ? (W + 4) : WPMIN;  // conv1:104 conv2:56
    constexpr int NOCQ  = OC_BLOCK / OPT;
    const float* in  = (SEL == 0) ? g_imgs : g_y1;
    float*       out = (SEL == 0) ? g_y1   : g_y2;
    const int total_oc = (SEL == 0) ? 16 : 32;

    extern __shared__ float smc[];
    float* tile = smc;                        // IC*TR*WP
    float* wsm  = tile + IC * TR * WP;        // OC_BLOCK*IC*28
    float* bsm  = wsm + OC_BLOCK * IC * 28;   // OC_BLOCK

    const int img = blockIdx.x, rg = blockIdx.y, ocg = blockIdx.z;
    const int prStart = rg * PR;
    const int ocStart = ocg * OC_BLOCK;
    const int tid = threadIdx.x;

    for (int idx = tid; idx < OC_BLOCK * IC * 28; idx += blockDim.x) {
        const int oc = idx / (IC * 28);
        const int r  = idx % (IC * 28);
        const int ic = r / 28, k = r % 28;
        wsm[idx] = (k < 25) ? wts[((ocStart + oc) * IC + ic) * 25 + k] : 0.f;
    }
    if (tid < OC_BLOCK) bsm[tid] = bias[ocStart + tid];

    const int y0 = prStart * 2 - 2;
    for (int idx = tid; idx < IC * TR * WP; idx += blockDim.x) {
        const int ic = idx / (TR * WP);
        const int r  = (idx / WP) % TR;
        const int c  = idx % WP;
        const int y = y0 + r, xx = c - 2;
        float v = 0.f;
        if (y >= 0 && y < W && xx >= 0 && xx < W)
            v = in[((img * IC + ic) * W + y) * W + xx];
        tile[idx] = v;
    }
    __syncthreads();

    // one position per thread: tid -> (pair, pr, ocq)
    const int pair = tid % NPAIR;
    const int pr   = (tid / NPAIR) % PR;
    const int ocq  = tid / (NPAIR * PR);

    const int ty = 2 * pr;
    const int tx = 4 * pair;

    float acc[OPT][8];   // [oc][quadA 0..3, quadB 4..7]
    #pragma unroll
    for (int o = 0; o < OPT; ++o)
        #pragma unroll
        for (int q = 0; q < 8; ++q) acc[o][q] = 0.f;

    const float* tp0 = tile + ty * WP + tx;
    const float* wb0 = wsm + ocq * OPT * IC * 28;

    #pragma unroll 1
    for (int ic = 0; ic < IC; ++ic) {
        float pf[6][8];
        const float* tp = tp0 + ic * TR * WP;
        #pragma unroll
        for (int r = 0; r < 6; ++r) {
            float4 a = *reinterpret_cast<const float4*>(tp + r * WP);
            float4 b = *reinterpret_cast<const float4*>(tp + r * WP + 4);
            pf[r][0] = a.x; pf[r][1] = a.y; pf[r][2] = a.z; pf[r][3] = a.w;
            pf[r][4] = b.x; pf[r][5] = b.y; pf[r][6] = b.z; pf[r][7] = b.w;
        }
        #pragma unroll
        for (int o = 0; o < OPT; ++o) {
            const float4* w4 = reinterpret_cast<const float4*>(
                wb0 + (o * IC + ic) * 28);
            float wv[28];
            #pragma unroll
            for (int q = 0; q < 7; ++q)
                *reinterpret_cast<float4*>(wv + 4 * q) = w4[q];
            #pragma unroll
            for (int ky = 0; ky < 5; ++ky)
                #pragma unroll
                for (int kx = 0; kx < 5; ++kx) {
                    const float w = wv[ky * 5 + kx];
                    acc[o][0] += pf[ky][kx]         * w;
                    acc[o][1] += pf[ky][kx + 1]     * w;
                    acc[o][2] += pf[ky + 1][kx]     * w;
                    acc[o][3] += pf[ky + 1][kx + 1] * w;
                    acc[o][4] += pf[ky][kx + 2]     * w;
                    acc[o][5] += pf[ky][kx + 3]     * w;
                    acc[o][6] += pf[ky + 1][kx + 2] * w;
                    acc[o][7] += pf[ky + 1][kx + 3] * w;
                }
        }
    }

    const int prow = prStart + pr;
    if (prow < PC) {
        const int pcA = 2 * pair;
        const int pcB = pcA + 1;
        #pragma unroll
        for (int o = 0; o < OPT; ++o) {
            const int oc = ocStart + ocq * OPT + o;
            const float bv = bsm[ocq * OPT + o];
            float* orow = out + ((img * total_oc + oc) * PC + prow) * PC;
            float mA = fmaxf(fmaxf(acc[o][0], acc[o][1]),
                             fmaxf(acc[o][2], acc[o][3])) + bv;
            orow[pcA] = fmaxf(mA, 0.f);
            if (pcB < PC) {
                float mB = fmaxf(fmaxf(acc[o][4], acc[o][5]),
                                 fmaxf(acc[o][6], acc[o][7])) + bv;
                orow[pcB] = fmaxf(mB, 0.f);
            }
        }
    }
}

// ======================= K5: FC head ========================================
__global__ __launch_bounds__(256) void fc_kernel(
    const float* __restrict__ w, const float* __restrict__ b,
    float* __restrict__ out)
{
    const int bc = blockIdx.x;
    const int bi = bc / NCLS, c = bc % NCLS;
    const float4* yb = reinterpret_cast<const float4*>(g_y2 + bi * 20000);
    const float4* wc = reinterpret_cast<const float4*>(w + c * 20000);
    float s = 0.f;
    for (int k = threadIdx.x; k < 5000; k += 256) {
        float4 a = yb[k], ww = wc[k];
        s += a.x * ww.x + a.y * ww.y + a.z * ww.z + a.w * ww.w;
    }
    #pragma unroll
    for (int off = 16; off; off >>= 1)
        s += __shfl_down_sync(0xffffffffu, s, off);
    __shared__ float red[8];
    if ((threadIdx.x & 31) == 0) red[threadIdx.x >> 5] = s;
    __syncthreads();
    if (threadIdx.x == 0) {
        float t = 0.f;
        #pragma unroll
        for (int wi = 0; wi < 8; ++wi) t += red[wi];
        out[bi * NCLS + c] = t + b[c];
    }
}

// ============================== launch ======================================
extern "C" void kernel_launch(void* const* d_in, const int* in_sizes, int n_in,
                              void* d_out, int out_size)
{
    const float* x        = (const float*)d_in[0];
    const int*   pidx0    = (const int*)  d_in[1];
    const int*   pidx1    = (const int*)  d_in[2];
    const float* w1       = (const float*)d_in[3];
    const float* b1       = (const float*)d_in[4];
    const float* w2       = (const float*)d_in[5];
    const float* b2       = (const float*)d_in[6];
    const float* conv1_w  = (const float*)d_in[7];
    const float* conv1_b  = (const float*)d_in[8];
    const float* conv2_w  = (const float*)d_in[9];
    const float* conv2_b  = (const float*)d_in[10];
    const float* out_w    = (const float*)d_in[11];
    const float* out_b    = (const float*)d_in[12];
    float* out = (float*)d_out;

    const int pers_smem  = PERS_SMEM_FLOATS * 4;                      // 103552
    // conv1: IC=2,W=100,PR=2 -> tile 2*8*104, w 16*2*28
    const int conv1_smem = (2 * 8 * 104 + 16 * 2 * 28 + 16) * 4;     // 10304
    // conv2: IC=16,W=50,PR=4 -> tile 16*12*56, w 16*16*28
    const int conv2_smem = (16 * 12 * 56 + 16 * 16 * 28 + 16) * 4;   // 71744

    cudaFuncSetAttribute(pers_image_kernel,
        cudaFuncAttributeMaxDynamicSharedMemorySize, pers_smem);
    cudaFuncSetAttribute((const void*)conv_pool_kernel<16, 50, 16, 4, 1>,
        cudaFuncAttributeMaxDynamicSharedMemorySize, conv2_smem);

    // K1: node filtration -> g_filt and d_out[320:]
    filt_kernel<<<250, 256>>>(x, w1, b1, w2, b2, out + BB * NCLS);

    // K2: persistence images -> g_imgs [B,2,100,100]
    pers_image_kernel<<<64, 256, pers_smem>>>(pidx0, pidx1);

    // K3: conv1 + relu + pool  [B,2,100,100] -> [B,16,50,50]
    // 200 threads = PR(2) * NPAIR(25) * NOCQ(4)
    conv_pool_kernel<2, 100, 16, 2, 0><<<dim3(32, 25, 1), 200, conv1_smem>>>(
        conv1_w, conv1_b);

    // K4: conv2 + relu + pool  [B,16,50,50] -> [B,32,25,25]
    // 208 threads = PR(4) * NPAIR(13) * NOCQ(4)
    conv_pool_kernel<16, 50, 16, 4, 1><<<dim3(32, 7, 2), 208, conv2_smem>>>(
        conv2_w, conv2_b);

    // K5: FC -> d_out[0:320]
    fc_kernel<<<BB * NCLS, 256>>>(out_w, out_b, out);
}

// round 7
// speedup vs baseline: 1.2381x; 1.2381x over previous
#include <cuda_runtime.h>
#include <cstdint>

#define NN     16000
#define IN_DIM 128
#define HID    64
#define BB     32
#define PP     128
#define DD     100
#define NCLS   10
#define INV_PI 0.31830988618379067f

// ---------------- scratch (device globals; no allocation allowed) -----------
__device__ float g_filt[NN];
__device__ float g_imgs[BB * 2 * DD * DD];
__device__ float g_y1[BB * 16 * 50 * 50];
__device__ float g_y2[BB * 32 * 25 * 25];

// ======================= K1: node filtration MLP ============================
__global__ __launch_bounds__(256) void filt_kernel(
    const float* __restrict__ x, const float* __restrict__ w1,
    const float* __restrict__ b1, const float* __restrict__ w2,
    const float* __restrict__ b2, float* __restrict__ out_filt)
{
    const int tid   = threadIdx.x;
    const int j     = tid & 63;
    const int chunk = tid >> 6;

    float wr[32];
    #pragma unroll
    for (int k = 0; k < 32; ++k)
        wr[k] = w1[(chunk * 32 + k) * HID + j];
    const float b1j = b1[j];
    const float w2j = w2[j];
    const float b2v = b2[0];

    __shared__ float xs[4][IN_DIM];
    __shared__ float part[4][4 * 64];
    __shared__ float nsum[4][2];

    for (int grp = 0; grp < 16; ++grp) {
        const int nbase = blockIdx.x * 64 + grp * 4;
        __syncthreads();
        for (int idx = tid; idx < 4 * IN_DIM; idx += 256) {
            int n = idx >> 7, c = idx & 127;
            xs[n][c] = x[(nbase + n) * IN_DIM + c];
        }
        __syncthreads();

        #pragma unroll
        for (int n = 0; n < 4; ++n) {
            const float4* xp = reinterpret_cast<const float4*>(xs[n] + chunk * 32);
            float s = 0.f;
            #pragma unroll
            for (int q = 0; q < 8; ++q) {
                float4 v = xp[q];
                s += v.x * wr[4 * q] + v.y * wr[4 * q + 1]
                   + v.z * wr[4 * q + 2] + v.w * wr[4 * q + 3];
            }
            part[n][chunk * 64 + j] = s;
        }
        __syncthreads();

        {
            const int n2 = chunk;
            float v = part[n2][j] + part[n2][64 + j]
                    + part[n2][128 + j] + part[n2][192 + j] + b1j;
            float h = fmaxf(v, 0.f) * w2j;
            #pragma unroll
            for (int off = 16; off; off >>= 1)
                h += __shfl_down_sync(0xffffffffu, h, off);
            if ((j & 31) == 0) nsum[n2][j >> 5] = h;
        }
        __syncthreads();
        if (tid < 4) {
            const int node = nbase + tid;
            float t = nsum[tid][0] + nsum[tid][1] + b2v;
            float f = 1.f / (1.f + __expf(-t));
            g_filt[node]   = f;
            out_filt[node] = f;
        }
    }
}

// ================ K2: persistence image (gather + exp + GEMM + norm) ========
#define PERS_SMEM_FLOATS (2 * PP * DD + PP + PP + 32)
__global__ __launch_bounds__(256) void pers_image_kernel(
    const int* __restrict__ pidx0, const int* __restrict__ pidx1)
{
    extern __shared__ float sm[];
    float* Us = sm;
    float* Vs = Us + PP * DD;
    float* bs = Vs + PP * DD;
    float* ps = bs + PP;
    float* red = ps + PP;

    const int m  = blockIdx.x;
    const int b  = m >> 1;
    const int ch = m & 1;
    const int* pidx = ch ? pidx1 : pidx0;
    const int tid = threadIdx.x;

    if (tid < PP) {
        int i0 = pidx[(b * PP + tid) * 2 + 0];
        int i1 = pidx[(b * PP + tid) * 2 + 1];
        float birth = g_filt[i0];
        bs[tid] = birth;
        ps[tid] = g_filt[i1] - birth;
    }
    __syncthreads();

    for (int idx = tid; idx < PP * DD; idx += 256) {
        int p = idx / DD, t = idx % DD;
        float c  = (float)t * 0.01f;
        float db = bs[p] - c;
        float dp = ps[p] - c;
        Us[idx] = __expf(-db * db);
        Vs[idx] = INV_PI * __expf(-dp * dp);
    }
    __syncthreads();

    float tv[48];
    float mx = 0.f;
    #pragma unroll
    for (int it = 0; it < 3; ++it) {
        const int tile = tid + it * 256;
        if (tile < 625) {
            const int i0 = (tile / 25) * 4;
            const int j0 = (tile % 25) * 4;
            float acc[16];
            #pragma unroll
            for (int k = 0; k < 16; ++k) acc[k] = 0.f;
            #pragma unroll 4
            for (int p = 0; p < PP; ++p) {
                float4 u = *reinterpret_cast<const float4*>(Us + p * DD + i0);
                float4 v = *reinterpret_cast<const float4*>(Vs + p * DD + j0);
                acc[0]  += u.x * v.x; acc[1]  += u.x * v.y; acc[2]  += u.x * v.z; acc[3]  += u.x * v.w;
                acc[4]  += u.y * v.x; acc[5]  += u.y * v.y; acc[6]  += u.y * v.z; acc[7]  += u.y * v.w;
                acc[8]  += u.z * v.x; acc[9]  += u.z * v.y; acc[10] += u.z * v.z; acc[11] += u.z * v.w;
                acc[12] += u.w * v.x; acc[13] += u.w * v.y; acc[14] += u.w * v.z; acc[15] += u.w * v.w;
            }
            #pragma unroll
            for (int k = 0; k < 16; ++k) {
                tv[it * 16 + k] = acc[k];
                mx = fmaxf(mx, acc[k]);
            }
        }
    }
    #pragma unroll
    for (int off = 16; off; off >>= 1)
        mx = fmaxf(mx, __shfl_down_sync(0xffffffffu, mx, off));
    if ((tid & 31) == 0) red[tid >> 5] = mx;
    __syncthreads();
    if (tid == 0) {
        float t = red[0];
        #pragma unroll
        for (int w = 1; w < 8; ++w) t = fmaxf(t, red[w]);
        red[0] = t;
    }
    __syncthreads();
    const float inv = 1.f / red[0];

    float* outp = g_imgs + m * (DD * DD);
    #pragma unroll
    for (int it = 0; it < 3; ++it) {
        const int tile = tid + it * 256;
        if (tile < 625) {
            const int i0 = (tile / 25) * 4;
            const int j0 = (tile % 25) * 4;
            #pragma unroll
            for (int a = 0; a < 4; ++a)
                #pragma unroll
                for (int c = 0; c < 4; ++c)
                    outp[(i0 + a) * DD + (j0 + c)] = tv[it * 16 + a * 4 + c] * inv;
        }
    }
}

// ============= K3: conv1 (R4-proven scalar) =================================
template<int IC, int W, int OC_BLOCK, int PR, int SEL>
__global__ __launch_bounds__(224, 2) void conv_pool_kernel(
    const float* __restrict__ wts, const float* __restrict__ bias)
{
    constexpr int OPT = 4;
    constexpr int TR  = 2 * PR + 4;
    constexpr int WP  = W + 4;
    constexpr int PC  = W / 2;
    constexpr int NOCQ = OC_BLOCK / OPT;
    const float* in  = (SEL == 0) ? g_imgs : g_y1;
    float*       out = (SEL == 0) ? g_y1   : g_y2;
    const int total_oc = (SEL == 0) ? 16 : 32;

    extern __shared__ float smc[];
    float* tile = smc;
    float* wsm  = tile + IC * TR * WP;
    float* bsm  = wsm + OC_BLOCK * IC * 28;

    const int img = blockIdx.x, rg = blockIdx.y, ocg = blockIdx.z;
    const int prStart = rg * PR;
    const int ocStart = ocg * OC_BLOCK;
    const int tid = threadIdx.x;

    for (int idx = tid; idx < OC_BLOCK * IC * 28; idx += blockDim.x) {
        const int oc = idx / (IC * 28);
        const int r  = idx % (IC * 28);
        const int ic = r / 28, k = r % 28;
        wsm[idx] = (k < 25) ? wts[((ocStart + oc) * IC + ic) * 25 + k] : 0.f;
    }
    if (tid < OC_BLOCK) bsm[tid] = bias[ocStart + tid];

    const int y0 = prStart * 2 - 2;
    for (int idx = tid; idx < IC * TR * WP; idx += blockDim.x) {
        const int ic = idx / (TR * WP);
        const int r  = (idx / WP) % TR;
        const int c  = idx % WP;
        const int y = y0 + r, xx = c - 2;
        float v = 0.f;
        if (y >= 0 && y < W && xx >= 0 && xx < W)
            v = in[((img * IC + ic) * W + y) * W + xx];
        tile[idx] = v;
    }
    __syncthreads();

    const int nPos = PR * PC * NOCQ;
    for (int pos = tid; pos < nPos; pos += blockDim.x) {
        const int sp  = pos % (PR * PC);
        const int ocq = pos / (PR * PC);
        const int pr = sp / PC, pc = sp % PC;
        if (prStart + pr >= PC) continue;
        const int ty = 2 * pr, tx = 2 * pc;

        float acc[OPT][4];
        #pragma unroll
        for (int o = 0; o < OPT; ++o)
            acc[o][0] = acc[o][1] = acc[o][2] = acc[o][3] = 0.f;

        #pragma unroll 1
        for (int ic = 0; ic < IC; ++ic) {
            float patch[6][6];
            const float* tp = tile + (ic * TR + ty) * WP + tx;
            #pragma unroll
            for (int r = 0; r < 6; ++r) {
                float2 a = *reinterpret_cast<const float2*>(tp + r * WP);
                float2 bq = *reinterpret_cast<const float2*>(tp + r * WP + 2);
                float2 c = *reinterpret_cast<const float2*>(tp + r * WP + 4);
                patch[r][0] = a.x;  patch[r][1] = a.y;
                patch[r][2] = bq.x; patch[r][3] = bq.y;
                patch[r][4] = c.x;  patch[r][5] = c.y;
            }
            #pragma unroll
            for (int o = 0; o < OPT; ++o) {
                const float4* w4 = reinterpret_cast<const float4*>(
                    wsm + ((ocq * OPT + o) * IC + ic) * 28);
                float wv[28];
                #pragma unroll
                for (int q = 0; q < 7; ++q)
                    *reinterpret_cast<float4*>(wv + 4 * q) = w4[q];
                #pragma unroll
                for (int ky = 0; ky < 5; ++ky)
                    #pragma unroll
                    for (int kx = 0; kx < 5; ++kx) {
                        const float wgt = wv[ky * 5 + kx];
                        acc[o][0] += patch[ky][kx]         * wgt;
                        acc[o][1] += patch[ky][kx + 1]     * wgt;
                        acc[o][2] += patch[ky + 1][kx]     * wgt;
                        acc[o][3] += patch[ky + 1][kx + 1] * wgt;
                    }
            }
        }
        #pragma unroll
        for (int o = 0; o < OPT; ++o) {
            const int oc = ocStart + ocq * OPT + o;
            float mv = fmaxf(fmaxf(acc[o][0], acc[o][1]),
                             fmaxf(acc[o][2], acc[o][3])) + bsm[ocq * OPT + o];
            mv = fmaxf(mv, 0.f);
            out[((img * total_oc + oc) * PC + (prStart + pr)) * PC + pc] = mv;
        }
    }
}

// ============= K4: conv2 as tf32 mma.sync implicit GEMM =====================
// cvt.rna.tf32.f32 needs a .b32 destination -> return uint32_t.
__device__ __forceinline__ uint32_t to_tf32(float x) {
    uint32_t r;
    asm("cvt.rna.tf32.f32 %0, %1;" : "=r"(r) : "f"(x));
    return r;
}
__device__ __forceinline__ void mma_tf32(
    float* d, const uint32_t* a, const uint32_t* b)
{
    asm volatile(
        "mma.sync.aligned.m16n8k8.row.col.f32.tf32.tf32.f32 "
        "{%0,%1,%2,%3}, {%4,%5,%6,%7}, {%8,%9}, {%0,%1,%2,%3};\n"
        : "+f"(d[0]), "+f"(d[1]), "+f"(d[2]), "+f"(d[3])
        : "r"(a[0]), "r"(a[1]), "r"(a[2]), "r"(a[3]),
          "r"(b[0]), "r"(b[1]));
}

#define C2_SMEM_FLOATS (16*8*56 + 400*33 + 208*33 + 400 + 32)
__global__ __launch_bounds__(256, 2) void conv2_tc_kernel(
    const float* __restrict__ wts, const float* __restrict__ bias)
{
    extern __shared__ float s[];
    float* tile = s;                         // [16][8][56] = 7168
    float* wB   = tile + 16 * 8 * 56;        // [400][33]   = 13200
    float* Cs   = wB + 400 * 33;             // [208][33]   = 6864
    int*   offs = (int*)(Cs + 208 * 33);     // [400]
    float* bsm  = (float*)(offs + 400);      // [32]

    const int img = blockIdx.x;
    const int prg = blockIdx.y;              // pooled-row pair index (0..12)
    const int tid = threadIdx.x;
    const int lane = tid & 31, warp = tid >> 5;
    const int grp = lane >> 2, qid = lane & 3;

    // B: wB[k][n] = tf32(conv2_w[n][k])
    for (int i = tid; i < 400 * 32; i += 256) {
        int k = i >> 5, n = i & 31;
        wB[k * 33 + n] = __uint_as_float(to_tf32(wts[n * 400 + k]));
    }
    if (tid < 32) bsm[tid] = bias[tid];
    for (int k = tid; k < 400; k += 256) {
        int ic = k / 25, kk = k % 25;
        offs[k] = ic * (8 * 56) + (kk / 5) * 56 + (kk % 5);
    }
    // input tile rows iy0..iy0+7 (halo for 4 conv rows), tf32-rounded
    const int iy0 = 4 * prg - 2;
    for (int i = tid; i < 16 * 8 * 56; i += 256) {
        int ic = i / (8 * 56), r = (i / 56) % 8, c = i % 56;
        int iy = iy0 + r, ix = c - 2;
        float v = 0.f;
        if (iy >= 0 && iy < 50 && ix >= 0 && ix < 50)
            v = g_y1[((img * 16 + ic) * 50 + iy) * 50 + ix];
        tile[i] = __uint_as_float(to_tf32(v));
    }
    __syncthreads();

    // A row base addresses: h = {tile0 row grp, tile0 row grp+8, tile1 ...}
    int abase[4];
    #pragma unroll
    for (int h = 0; h < 4; ++h) {
        int mt = warp + (h >> 1) * 8;
        int m = mt * 16 + grp + (h & 1) * 8;
        if (m > 199) m = 199;                // pad rows: duplicate, never stored
        abase[h] = (m / 50) * 56 + (m % 50);
    }

    float acc[2][4][4];
    #pragma unroll
    for (int t = 0; t < 2; ++t)
        #pragma unroll
        for (int nt = 0; nt < 4; ++nt)
            acc[t][nt][0] = acc[t][nt][1] = acc[t][nt][2] = acc[t][nt][3] = 0.f;

    #pragma unroll 2
    for (int ks = 0; ks < 50; ++ks) {
        const int o0 = offs[ks * 8 + qid];
        const int o1 = offs[ks * 8 + qid + 4];

        uint32_t a[2][4];
        #pragma unroll
        for (int t = 0; t < 2; ++t) {
            a[t][0] = __float_as_uint(tile[abase[t * 2]     + o0]);
            a[t][1] = __float_as_uint(tile[abase[t * 2 + 1] + o0]);
            a[t][2] = __float_as_uint(tile[abase[t * 2]     + o1]);
            a[t][3] = __float_as_uint(tile[abase[t * 2 + 1] + o1]);
        }
        const float* wr0 = wB + (ks * 8 + qid) * 33 + grp;
        uint32_t b[4][2];
        #pragma unroll
        for (int nt = 0; nt < 4; ++nt) {
            b[nt][0] = __float_as_uint(wr0[nt * 8]);
            b[nt][1] = __float_as_uint(wr0[4 * 33 + nt * 8]);
        }
        #pragma unroll
        for (int t = 0; t < 2; ++t)
            #pragma unroll
            for (int nt = 0; nt < 4; ++nt)
                mma_tf32(acc[t][nt], a[t], b[nt]);
    }

    // stage conv outputs to smem (stride 33)
    #pragma unroll
    for (int t = 0; t < 2; ++t) {
        const int mt = warp + t * 8;
        const int m0 = mt * 16 + grp;
        if (m0 < 208) {
            #pragma unroll
            for (int nt = 0; nt < 4; ++nt) {
                const int n0 = nt * 8 + 2 * qid;
                Cs[m0 * 33 + n0]           = acc[t][nt][0];
                Cs[m0 * 33 + n0 + 1]       = acc[t][nt][1];
                Cs[(m0 + 8) * 33 + n0]     = acc[t][nt][2];
                Cs[(m0 + 8) * 33 + n0 + 1] = acc[t][nt][3];
            }
        }
    }
    __syncthreads();

    // fused bias + 2x2 maxpool + relu
    for (int idx = tid; idx < 1600; idx += 256) {
        const int oc = idx & 31;
        const int pc = (idx >> 5) % 25;
        const int prl = idx / 800;
        const int prow = 2 * prg + prl;
        if (prow < 25) {
            const int m00 = 2 * prl * 50 + 2 * pc;
            float v = fmaxf(fmaxf(Cs[m00 * 33 + oc],        Cs[(m00 + 1) * 33 + oc]),
                            fmaxf(Cs[(m00 + 50) * 33 + oc], Cs[(m00 + 51) * 33 + oc]));
            v = fmaxf(v + bsm[oc], 0.f);
            g_y2[((img * 32 + oc) * 25 + prow) * 25 + pc] = v;
        }
    }
}

// ======================= K5: FC head ========================================
__global__ __launch_bounds__(256) void fc_kernel(
    const float* __restrict__ w, const float* __restrict__ b,
    float* __restrict__ out)
{
    const int bc = blockIdx.x;
    const int bi = bc / NCLS, c = bc % NCLS;
    const float4* yb = reinterpret_cast<const float4*>(g_y2 + bi * 20000);
    const float4* wc = reinterpret_cast<const float4*>(w + c * 20000);
    float s = 0.f;
    for (int k = threadIdx.x; k < 5000; k += 256) {
        float4 a = yb[k], ww = wc[k];
        s += a.x * ww.x + a.y * ww.y + a.z * ww.z + a.w * ww.w;
    }
    #pragma unroll
    for (int off = 16; off; off >>= 1)
        s += __shfl_down_sync(0xffffffffu, s, off);
    __shared__ float red[8];
    if ((threadIdx.x & 31) == 0) red[threadIdx.x >> 5] = s;
    __syncthreads();
    if (threadIdx.x == 0) {
        float t = 0.f;
        #pragma unroll
        for (int wi = 0; wi < 8; ++wi) t += red[wi];
        out[bi * NCLS + c] = t + b[c];
    }
}

// ============================== launch ======================================
extern "C" void kernel_launch(void* const* d_in, const int* in_sizes, int n_in,
                              void* d_out, int out_size)
{
    const float* x        = (const float*)d_in[0];
    const int*   pidx0    = (const int*)  d_in[1];
    const int*   pidx1    = (const int*)  d_in[2];
    const float* w1       = (const float*)d_in[3];
    const float* b1       = (const float*)d_in[4];
    const float* w2       = (const float*)d_in[5];
    const float* b2       = (const float*)d_in[6];
    const float* conv1_w  = (const float*)d_in[7];
    const float* conv1_b  = (const float*)d_in[8];
    const float* conv2_w  = (const float*)d_in[9];
    const float* conv2_b  = (const float*)d_in[10];
    const float* out_w    = (const float*)d_in[11];
    const float* out_b    = (const float*)d_in[12];
    float* out = (float*)d_out;

    const int pers_smem  = PERS_SMEM_FLOATS * 4;                      // 103552
    const int conv1_smem = (2 * 8 * 104 + 16 * 2 * 28 + 16) * 4;     // 10304
    const int conv2_smem = C2_SMEM_FLOATS * 4;                        // 110656

    cudaFuncSetAttribute(pers_image_kernel,
        cudaFuncAttributeMaxDynamicSharedMemorySize, pers_smem);
    cudaFuncSetAttribute(conv2_tc_kernel,
        cudaFuncAttributeMaxDynamicSharedMemorySize, conv2_smem);

    // K1: node filtration -> g_filt and d_out[320:]
    filt_kernel<<<250, 256>>>(x, w1, b1, w2, b2, out + BB * NCLS);

    // K2: persistence images -> g_imgs [B,2,100,100]
    pers_image_kernel<<<64, 256, pers_smem>>>(pidx0, pidx1);

    // K3: conv1 + relu + pool  [B,2,100,100] -> [B,16,50,50]  (scalar, proven)
    conv_pool_kernel<2, 100, 16, 2, 0><<<dim3(32, 25, 1), 224, conv1_smem>>>(
        conv1_w, conv1_b);

    // K4: conv2 via tf32 tensor cores  [B,16,50,50] -> [B,32,25,25]
    conv2_tc_kernel<<<dim3(32, 13), 256, conv2_smem>>>(conv2_w, conv2_b);

    // K5: FC -> d_out[0:320]
    fc_kernel<<<BB * NCLS, 256>>>(out_w, out_b, out);
}

// round 8
// speedup vs baseline: 1.4182x; 1.1455x over previous
#include <cuda_runtime.h>
#include <cstdint>

#define NN     16000
#define IN_DIM 128
#define HID    64
#define BB     32
#define PP     128
#define DD     100
#define NCLS   10
#define INV_PI 0.31830988618379067f

// ---------------- scratch (device globals; no allocation allowed) -----------
__device__ float g_filt[NN];
__device__ float g_imgs[BB * 2 * DD * DD];
__device__ float g_y1[BB * 16 * 50 * 50];
__device__ float g_y2[BB * 32 * 25 * 25];

// ======================= K1: node filtration MLP ============================
__global__ __launch_bounds__(256) void filt_kernel(
    const float* __restrict__ x, const float* __restrict__ w1,
    const float* __restrict__ b1, const float* __restrict__ w2,
    const float* __restrict__ b2, float* __restrict__ out_filt)
{
    const int tid   = threadIdx.x;
    const int j     = tid & 63;
    const int chunk = tid >> 6;

    float wr[32];
    #pragma unroll
    for (int k = 0; k < 32; ++k)
        wr[k] = w1[(chunk * 32 + k) * HID + j];
    const float b1j = b1[j];
    const float w2j = w2[j];
    const float b2v = b2[0];

    __shared__ float xs[4][IN_DIM];
    __shared__ float part[4][4 * 64];
    __shared__ float nsum[4][2];

    for (int grp = 0; grp < 16; ++grp) {
        const int nbase = blockIdx.x * 64 + grp * 4;
        __syncthreads();
        for (int idx = tid; idx < 4 * IN_DIM; idx += 256) {
            int n = idx >> 7, c = idx & 127;
            xs[n][c] = x[(nbase + n) * IN_DIM + c];
        }
        __syncthreads();

        #pragma unroll
        for (int n = 0; n < 4; ++n) {
            const float4* xp = reinterpret_cast<const float4*>(xs[n] + chunk * 32);
            float s = 0.f;
            #pragma unroll
            for (int q = 0; q < 8; ++q) {
                float4 v = xp[q];
                s += v.x * wr[4 * q] + v.y * wr[4 * q + 1]
                   + v.z * wr[4 * q + 2] + v.w * wr[4 * q + 3];
            }
            part[n][chunk * 64 + j] = s;
        }
        __syncthreads();

        {
            const int n2 = chunk;
            float v = part[n2][j] + part[n2][64 + j]
                    + part[n2][128 + j] + part[n2][192 + j] + b1j;
            float h = fmaxf(v, 0.f) * w2j;
            #pragma unroll
            for (int off = 16; off; off >>= 1)
                h += __shfl_down_sync(0xffffffffu, h, off);
            if ((j & 31) == 0) nsum[n2][j >> 5] = h;
        }
        __syncthreads();
        if (tid < 4) {
            const int node = nbase + tid;
            float t = nsum[tid][0] + nsum[tid][1] + b2v;
            float f = 1.f / (1.f + __expf(-t));
            g_filt[node]   = f;
            out_filt[node] = f;
        }
    }
}

// ================ K2: persistence image (gather + exp + GEMM + norm) ========
#define PERS_SMEM_FLOATS (2 * PP * DD + PP + PP + 32)
__global__ __launch_bounds__(256) void pers_image_kernel(
    const int* __restrict__ pidx0, const int* __restrict__ pidx1)
{
    extern __shared__ float sm[];
    float* Us = sm;
    float* Vs = Us + PP * DD;
    float* bs = Vs + PP * DD;
    float* ps = bs + PP;
    float* red = ps + PP;

    const int m  = blockIdx.x;
    const int b  = m >> 1;
    const int ch = m & 1;
    const int* pidx = ch ? pidx1 : pidx0;
    const int tid = threadIdx.x;

    if (tid < PP) {
        int i0 = pidx[(b * PP + tid) * 2 + 0];
        int i1 = pidx[(b * PP + tid) * 2 + 1];
        float birth = g_filt[i0];
        bs[tid] = birth;
        ps[tid] = g_filt[i1] - birth;
    }
    __syncthreads();

    for (int idx = tid; idx < PP * DD; idx += 256) {
        int p = idx / DD, t = idx % DD;
        float c  = (float)t * 0.01f;
        float db = bs[p] - c;
        float dp = ps[p] - c;
        Us[idx] = __expf(-db * db);
        Vs[idx] = INV_PI * __expf(-dp * dp);
    }
    __syncthreads();

    float tv[48];
    float mx = 0.f;
    #pragma unroll
    for (int it = 0; it < 3; ++it) {
        const int tile = tid + it * 256;
        if (tile < 625) {
            const int i0 = (tile / 25) * 4;
            const int j0 = (tile % 25) * 4;
            float acc[16];
            #pragma unroll
            for (int k = 0; k < 16; ++k) acc[k] = 0.f;
            #pragma unroll 4
            for (int p = 0; p < PP; ++p) {
                float4 u = *reinterpret_cast<const float4*>(Us + p * DD + i0);
                float4 v = *reinterpret_cast<const float4*>(Vs + p * DD + j0);
                acc[0]  += u.x * v.x; acc[1]  += u.x * v.y; acc[2]  += u.x * v.z; acc[3]  += u.x * v.w;
                acc[4]  += u.y * v.x; acc[5]  += u.y * v.y; acc[6]  += u.y * v.z; acc[7]  += u.y * v.w;
                acc[8]  += u.z * v.x; acc[9]  += u.z * v.y; acc[10] += u.z * v.z; acc[11] += u.z * v.w;
                acc[12] += u.w * v.x; acc[13] += u.w * v.y; acc[14] += u.w * v.z; acc[15] += u.w * v.w;
            }
            #pragma unroll
            for (int k = 0; k < 16; ++k) {
                tv[it * 16 + k] = acc[k];
                mx = fmaxf(mx, acc[k]);
            }
        }
    }
    #pragma unroll
    for (int off = 16; off; off >>= 1)
        mx = fmaxf(mx, __shfl_down_sync(0xffffffffu, mx, off));
    if ((tid & 31) == 0) red[tid >> 5] = mx;
    __syncthreads();
    if (tid == 0) {
        float t = red[0];
        #pragma unroll
        for (int w = 1; w < 8; ++w) t = fmaxf(t, red[w]);
        red[0] = t;
    }
    __syncthreads();
    const float inv = 1.f / red[0];

    float* outp = g_imgs + m * (DD * DD);
    #pragma unroll
    for (int it = 0; it < 3; ++it) {
        const int tile = tid + it * 256;
        if (tile < 625) {
            const int i0 = (tile / 25) * 4;
            const int j0 = (tile % 25) * 4;
            #pragma unroll
            for (int a = 0; a < 4; ++a)
                #pragma unroll
                for (int c = 0; c < 4; ++c)
                    outp[(i0 + a) * DD + (j0 + c)] = tv[it * 16 + a * 4 + c] * inv;
        }
    }
}

// ============= K3: conv1 (R4-proven scalar) =================================
template<int IC, int W, int OC_BLOCK, int PR, int SEL>
__global__ __launch_bounds__(224, 2) void conv_pool_kernel(
    const float* __restrict__ wts, const float* __restrict__ bias)
{
    constexpr int OPT = 4;
    constexpr int TR  = 2 * PR + 4;
    constexpr int WP  = W + 4;
    constexpr int PC  = W / 2;
    constexpr int NOCQ = OC_BLOCK / OPT;
    const float* in  = (SEL == 0) ? g_imgs : g_y1;
    float*       out = (SEL == 0) ? g_y1   : g_y2;
    const int total_oc = (SEL == 0) ? 16 : 32;

    extern __shared__ float smc[];
    float* tile = smc;
    float* wsm  = tile + IC * TR * WP;
    float* bsm  = wsm + OC_BLOCK * IC * 28;

    const int img = blockIdx.x, rg = blockIdx.y, ocg = blockIdx.z;
    const int prStart = rg * PR;
    const int ocStart = ocg * OC_BLOCK;
    const int tid = threadIdx.x;

    for (int idx = tid; idx < OC_BLOCK * IC * 28; idx += blockDim.x) {
        const int oc = idx / (IC * 28);
        const int r  = idx % (IC * 28);
        const int ic = r / 28, k = r % 28;
        wsm[idx] = (k < 25) ? wts[((ocStart + oc) * IC + ic) * 25 + k] : 0.f;
    }
    if (tid < OC_BLOCK) bsm[tid] = bias[ocStart + tid];

    const int y0 = prStart * 2 - 2;
    for (int idx = tid; idx < IC * TR * WP; idx += blockDim.x) {
        const int ic = idx / (TR * WP);
        const int r  = (idx / WP) % TR;
        const int c  = idx % WP;
        const int y = y0 + r, xx = c - 2;
        float v = 0.f;
        if (y >= 0 && y < W && xx >= 0 && xx < W)
            v = in[((img * IC + ic) * W + y) * W + xx];
        tile[idx] = v;
    }
    __syncthreads();

    const int nPos = PR * PC * NOCQ;
    for (int pos = tid; pos < nPos; pos += blockDim.x) {
        const int sp  = pos % (PR * PC);
        const int ocq = pos / (PR * PC);
        const int pr = sp / PC, pc = sp % PC;
        if (prStart + pr >= PC) continue;
        const int ty = 2 * pr, tx = 2 * pc;

        float acc[OPT][4];
        #pragma unroll
        for (int o = 0; o < OPT; ++o)
            acc[o][0] = acc[o][1] = acc[o][2] = acc[o][3] = 0.f;

        #pragma unroll 1
        for (int ic = 0; ic < IC; ++ic) {
            float patch[6][6];
            const float* tp = tile + (ic * TR + ty) * WP + tx;
            #pragma unroll
            for (int r = 0; r < 6; ++r) {
                float2 a = *reinterpret_cast<const float2*>(tp + r * WP);
                float2 bq = *reinterpret_cast<const float2*>(tp + r * WP + 2);
                float2 c = *reinterpret_cast<const float2*>(tp + r * WP + 4);
                patch[r][0] = a.x;  patch[r][1] = a.y;
                patch[r][2] = bq.x; patch[r][3] = bq.y;
                patch[r][4] = c.x;  patch[r][5] = c.y;
            }
            #pragma unroll
            for (int o = 0; o < OPT; ++o) {
                const float4* w4 = reinterpret_cast<const float4*>(
                    wsm + ((ocq * OPT + o) * IC + ic) * 28);
                float wv[28];
                #pragma unroll
                for (int q = 0; q < 7; ++q)
                    *reinterpret_cast<float4*>(wv + 4 * q) = w4[q];
                #pragma unroll
                for (int ky = 0; ky < 5; ++ky)
                    #pragma unroll
                    for (int kx = 0; kx < 5; ++kx) {
                        const float wgt = wv[ky * 5 + kx];
                        acc[o][0] += patch[ky][kx]         * wgt;
                        acc[o][1] += patch[ky][kx + 1]     * wgt;
                        acc[o][2] += patch[ky + 1][kx]     * wgt;
                        acc[o][3] += patch[ky + 1][kx + 1] * wgt;
                    }
            }
        }
        #pragma unroll
        for (int o = 0; o < OPT; ++o) {
            const int oc = ocStart + ocq * OPT + o;
            float mv = fmaxf(fmaxf(acc[o][0], acc[o][1]),
                             fmaxf(acc[o][2], acc[o][3])) + bsm[ocq * OPT + o];
            mv = fmaxf(mv, 0.f);
            out[((img * total_oc + oc) * PC + (prStart + pr)) * PC + pc] = mv;
        }
    }
}

// ============= K4: conv2 as tf32 mma.sync implicit GEMM =====================
__device__ __forceinline__ uint32_t to_tf32(float x) {
    uint32_t r;
    asm("cvt.rna.tf32.f32 %0, %1;" : "=r"(r) : "f"(x));
    return r;
}
__device__ __forceinline__ void mma_tf32(
    float* d, const uint32_t* a, const uint32_t* b)
{
    asm volatile(
        "mma.sync.aligned.m16n8k8.row.col.f32.tf32.tf32.f32 "
        "{%0,%1,%2,%3}, {%4,%5,%6,%7}, {%8,%9}, {%0,%1,%2,%3};\n"
        : "+f"(d[0]), "+f"(d[1]), "+f"(d[2]), "+f"(d[3])
        : "r"(a[0]), "r"(a[1]), "r"(a[2]), "r"(a[3]),
          "r"(b[0]), "r"(b[1]));
}

// smem: tile [16][8][57] (stride 57 kills quad conflicts), Bf [50][32][8]
// (B in fragment order -> 2x LDS.128 per K-step), offs[400], bsm[32].
// C staging buffer (208x33) ALIASES tile (dead after mainloop) -> 82.1 KB,
// 2 CTAs/SM.
#define C2_TILE       (16 * 8 * 57)
#define C2_SMEM_FLOATS (C2_TILE + 50 * 32 * 8 + 400 + 32)
__global__ __launch_bounds__(256, 2) void conv2_tc_kernel(
    const float* __restrict__ wts, const float* __restrict__ bias)
{
    extern __shared__ float s[];
    float* tile = s;                          // [16][8][57] = 7296
    float* Bf   = tile + C2_TILE;             // [50][32][8] = 12800
    int*   offs = (int*)(Bf + 50 * 32 * 8);   // [400]
    float* bsm  = (float*)(offs + 400);       // [32]
    float* Cs   = s;                          // alias of tile (used post-loop)

    const int img = blockIdx.x;
    const int prg = blockIdx.y;               // pooled-row pair index (0..12)
    const int tid = threadIdx.x;
    const int lane = tid & 31, warp = tid >> 5;
    const int grp = lane >> 2, qid = lane & 3;

    // B fragments: Bf[ks][lane][2*nt+h] = tf32(w[n = grp+8nt][k = 8ks+qid+4h])
    for (int idx = tid; idx < 50 * 32; idx += 256) {
        const int ks = idx >> 5, ln = idx & 31;
        const int g2 = ln >> 2, q2 = ln & 3;
        float v[8];
        #pragma unroll
        for (int nt = 0; nt < 4; ++nt) {
            const float* wp = wts + (g2 + 8 * nt) * 400 + 8 * ks + q2;
            v[2 * nt]     = __uint_as_float(to_tf32(wp[0]));
            v[2 * nt + 1] = __uint_as_float(to_tf32(wp[4]));
        }
        float* dst = Bf + idx * 8;
        *reinterpret_cast<float4*>(dst)     = *reinterpret_cast<float4*>(v);
        *reinterpret_cast<float4*>(dst + 4) = *reinterpret_cast<float4*>(v + 4);
    }
    if (tid < 32) bsm[tid] = bias[tid];
    for (int k = tid; k < 400; k += 256) {
        int ic = k / 25, kk = k % 25;
        offs[k] = ic * (8 * 57) + (kk / 5) * 57 + (kk % 5);
    }
    // input tile rows iy0..iy0+7 (halo for 4 conv rows), tf32-rounded
    const int iy0 = 4 * prg - 2;
    for (int i = tid; i < C2_TILE; i += 256) {
        int ic = i / 456, r = (i / 57) % 8, c = i % 57;
        int iy = iy0 + r, ix = c - 2;
        float v = 0.f;
        if (iy >= 0 && iy < 50 && ix >= 0 && ix < 50)
            v = g_y1[((img * 16 + ic) * 50 + iy) * 50 + ix];
        tile[i] = __uint_as_float(to_tf32(v));
    }
    __syncthreads();

    // A row base addresses
    int abase[4];
    #pragma unroll
    for (int h = 0; h < 4; ++h) {
        int mt = warp + (h >> 1) * 8;
        int m = mt * 16 + grp + (h & 1) * 8;
        if (m > 199) m = 199;
        abase[h] = (m / 50) * 57 + (m % 50);
    }

    float acc[2][4][4];
    #pragma unroll
    for (int t = 0; t < 2; ++t)
        #pragma unroll
        for (int nt = 0; nt < 4; ++nt)
            acc[t][nt][0] = acc[t][nt][1] = acc[t][nt][2] = acc[t][nt][3] = 0.f;

    #pragma unroll 2
    for (int ks = 0; ks < 50; ++ks) {
        const int o0 = offs[ks * 8 + qid];
        const int o1 = offs[ks * 8 + qid + 4];

        uint32_t a[2][4];
        #pragma unroll
        for (int t = 0; t < 2; ++t) {
            a[t][0] = __float_as_uint(tile[abase[t * 2]     + o0]);
            a[t][1] = __float_as_uint(tile[abase[t * 2 + 1] + o0]);
            a[t][2] = __float_as_uint(tile[abase[t * 2]     + o1]);
            a[t][3] = __float_as_uint(tile[abase[t * 2 + 1] + o1]);
        }
        const float4* bp = reinterpret_cast<const float4*>(
            Bf + (ks * 32 + lane) * 8);
        float4 bv0 = bp[0], bv1 = bp[1];
        uint32_t b[4][2];
        b[0][0] = __float_as_uint(bv0.x); b[0][1] = __float_as_uint(bv0.y);
        b[1][0] = __float_as_uint(bv0.z); b[1][1] = __float_as_uint(bv0.w);
        b[2][0] = __float_as_uint(bv1.x); b[2][1] = __float_as_uint(bv1.y);
        b[3][0] = __float_as_uint(bv1.z); b[3][1] = __float_as_uint(bv1.w);

        #pragma unroll
        for (int t = 0; t < 2; ++t)
            #pragma unroll
            for (int nt = 0; nt < 4; ++nt)
                mma_tf32(acc[t][nt], a[t], b[nt]);
    }

    __syncthreads();   // tile reads done everywhere; Cs may overwrite it

    #pragma unroll
    for (int t = 0; t < 2; ++t) {
        const int mt = warp + t * 8;
        const int m0 = mt * 16 + grp;
        if (m0 < 208) {
            #pragma unroll
            for (int nt = 0; nt < 4; ++nt) {
                const int n0 = nt * 8 + 2 * qid;
                Cs[m0 * 33 + n0]           = acc[t][nt][0];
                Cs[m0 * 33 + n0 + 1]       = acc[t][nt][1];
                Cs[(m0 + 8) * 33 + n0]     = acc[t][nt][2];
                Cs[(m0 + 8) * 33 + n0 + 1] = acc[t][nt][3];
            }
        }
    }
    __syncthreads();

    // fused bias + 2x2 maxpool + relu
    for (int idx = tid; idx < 1600; idx += 256) {
        const int oc = idx & 31;
        const int pc = (idx >> 5) % 25;
        const int prl = idx / 800;
        const int prow = 2 * prg + prl;
        if (prow < 25) {
            const int m00 = 2 * prl * 50 + 2 * pc;
            float v = fmaxf(fmaxf(Cs[m00 * 33 + oc],        Cs[(m00 + 1) * 33 + oc]),
                            fmaxf(Cs[(m00 + 50) * 33 + oc], Cs[(m00 + 51) * 33 + oc]));
            v = fmaxf(v + bsm[oc], 0.f);
            g_y2[((img * 32 + oc) * 25 + prow) * 25 + pc] = v;
        }
    }
}

// ======================= K5: FC head ========================================
__global__ __launch_bounds__(256) void fc_kernel(
    const float* __restrict__ w, const float* __restrict__ b,
    float* __restrict__ out)
{
    const int bc = blockIdx.x;
    const int bi = bc / NCLS, c = bc % NCLS;
    const float4* yb = reinterpret_cast<const float4*>(g_y2 + bi * 20000);
    const float4* wc = reinterpret_cast<const float4*>(w + c * 20000);
    float s = 0.f;
    for (int k = threadIdx.x; k < 5000; k += 256) {
        float4 a = yb[k], ww = wc[k];
        s += a.x * ww.x + a.y * ww.y + a.z * ww.z + a.w * ww.w;
    }
    #pragma unroll
    for (int off = 16; off; off >>= 1)
        s += __shfl_down_sync(0xffffffffu, s, off);
    __shared__ float red[8];
    if ((threadIdx.x & 31) == 0) red[threadIdx.x >> 5] = s;
    __syncthreads();
    if (threadIdx.x == 0) {
        float t = 0.f;
        #pragma unroll
        for (int wi = 0; wi < 8; ++wi) t += red[wi];
        out[bi * NCLS + c] = t + b[c];
    }
}

// ============================== launch ======================================
extern "C" void kernel_launch(void* const* d_in, const int* in_sizes, int n_in,
                              void* d_out, int out_size)
{
    const float* x        = (const float*)d_in[0];
    const int*   pidx0    = (const int*)  d_in[1];
    const int*   pidx1    = (const int*)  d_in[2];
    const float* w1       = (const float*)d_in[3];
    const float* b1       = (const float*)d_in[4];
    const float* w2       = (const float*)d_in[5];
    const float* b2       = (const float*)d_in[6];
    const float* conv1_w  = (const float*)d_in[7];
    const float* conv1_b  = (const float*)d_in[8];
    const float* conv2_w  = (const float*)d_in[9];
    const float* conv2_b  = (const float*)d_in[10];
    const float* out_w    = (const float*)d_in[11];
    const float* out_b    = (const float*)d_in[12];
    float* out = (float*)d_out;

    const int pers_smem  = PERS_SMEM_FLOATS * 4;                      // 103552
    const int conv1_smem = (2 * 8 * 104 + 16 * 2 * 28 + 16) * 4;     // 10304
    const int conv2_smem = C2_SMEM_FLOATS * 4;                        // 82112

    cudaFuncSetAttribute(pers_image_kernel,
        cudaFuncAttributeMaxDynamicSharedMemorySize, pers_smem);
    cudaFuncSetAttribute(conv2_tc_kernel,
        cudaFuncAttributeMaxDynamicSharedMemorySize, conv2_smem);

    // K1: node filtration -> g_filt and d_out[320:]
    filt_kernel<<<250, 256>>>(x, w1, b1, w2, b2, out + BB * NCLS);

    // K2: persistence images -> g_imgs [B,2,100,100]
    pers_image_kernel<<<64, 256, pers_smem>>>(pidx0, pidx1);

    // K3: conv1 + relu + pool  [B,2,100,100] -> [B,16,50,50]
    conv_pool_kernel<2, 100, 16, 2, 0><<<dim3(32, 25, 1), 224, conv1_smem>>>(
        conv1_w, conv1_b);

    // K4: conv2 via tf32 tensor cores  [B,16,50,50] -> [B,32,25,25]
    conv2_tc_kernel<<<dim3(32, 13), 256, conv2_smem>>>(conv2_w, conv2_b);

    // K5: FC -> d_out[0:320]
    fc_kernel<<<BB * NCLS, 256>>>(out_w, out_b, out);
}

// round 9
// speedup vs baseline: 1.5294x; 1.0784x over previous
#include <cuda_runtime.h>
#include <cstdint>

#define NN     16000
#define IN_DIM 128
#define HID    64
#define BB     32
#define PP     128
#define DD     100
#define NCLS   10
#define INV_PI 0.31830988618379067f

// ---------------- scratch (device globals; no allocation allowed) -----------
__device__ float g_filt[NN];
__device__ float g_imgs[BB * 2 * DD * DD];
__device__ float g_y1[BB * 16 * 50 * 50];
__device__ float g_y2[BB * 32 * 25 * 25];

// ======================= K1: node filtration MLP ============================
__global__ __launch_bounds__(256) void filt_kernel(
    const float* __restrict__ x, const float* __restrict__ w1,
    const float* __restrict__ b1, const float* __restrict__ w2,
    const float* __restrict__ b2, float* __restrict__ out_filt)
{
    const int tid   = threadIdx.x;
    const int j     = tid & 63;
    const int chunk = tid >> 6;

    float wr[32];
    #pragma unroll
    for (int k = 0; k < 32; ++k)
        wr[k] = w1[(chunk * 32 + k) * HID + j];
    const float b1j = b1[j];
    const float w2j = w2[j];
    const float b2v = b2[0];

    __shared__ float xs[4][IN_DIM];
    __shared__ float part[4][4 * 64];
    __shared__ float nsum[4][2];

    for (int grp = 0; grp < 16; ++grp) {
        const int nbase = blockIdx.x * 64 + grp * 4;
        __syncthreads();
        for (int idx = tid; idx < 4 * IN_DIM; idx += 256) {
            int n = idx >> 7, c = idx & 127;
            xs[n][c] = x[(nbase + n) * IN_DIM + c];
        }
        __syncthreads();

        #pragma unroll
        for (int n = 0; n < 4; ++n) {
            const float4* xp = reinterpret_cast<const float4*>(xs[n] + chunk * 32);
            float s = 0.f;
            #pragma unroll
            for (int q = 0; q < 8; ++q) {
                float4 v = xp[q];
                s += v.x * wr[4 * q] + v.y * wr[4 * q + 1]
                   + v.z * wr[4 * q + 2] + v.w * wr[4 * q + 3];
            }
            part[n][chunk * 64 + j] = s;
        }
        __syncthreads();

        {
            const int n2 = chunk;
            float v = part[n2][j] + part[n2][64 + j]
                    + part[n2][128 + j] + part[n2][192 + j] + b1j;
            float h = fmaxf(v, 0.f) * w2j;
            #pragma unroll
            for (int off = 16; off; off >>= 1)
                h += __shfl_down_sync(0xffffffffu, h, off);
            if ((j & 31) == 0) nsum[n2][j >> 5] = h;
        }
        __syncthreads();
        if (tid < 4) {
            const int node = nbase + tid;
            float t = nsum[tid][0] + nsum[tid][1] + b2v;
            float f = 1.f / (1.f + __expf(-t));
            g_filt[node]   = f;
            out_filt[node] = f;
        }
    }
}

// ================ K2: persistence image (gather + exp + GEMM + norm) ========
#define PERS_SMEM_FLOATS (2 * PP * DD + PP + PP + 32)
__global__ __launch_bounds__(256) void pers_image_kernel(
    const int* __restrict__ pidx0, const int* __restrict__ pidx1)
{
    extern __shared__ float sm[];
    float* Us = sm;
    float* Vs = Us + PP * DD;
    float* bs = Vs + PP * DD;
    float* ps = bs + PP;
    float* red = ps + PP;

    const int m  = blockIdx.x;
    const int b  = m >> 1;
    const int ch = m & 1;
    const int* pidx = ch ? pidx1 : pidx0;
    const int tid = threadIdx.x;

    if (tid < PP) {
        int i0 = pidx[(b * PP + tid) * 2 + 0];
        int i1 = pidx[(b * PP + tid) * 2 + 1];
        float birth = g_filt[i0];
        bs[tid] = birth;
        ps[tid] = g_filt[i1] - birth;
    }
    __syncthreads();

    for (int idx = tid; idx < PP * DD; idx += 256) {
        int p = idx / DD, t = idx % DD;
        float c  = (float)t * 0.01f;
        float db = bs[p] - c;
        float dp = ps[p] - c;
        Us[idx] = __expf(-db * db);
        Vs[idx] = INV_PI * __expf(-dp * dp);
    }
    __syncthreads();

    float tv[48];
    float mx = 0.f;
    #pragma unroll
    for (int it = 0; it < 3; ++it) {
        const int tile = tid + it * 256;
        if (tile < 625) {
            const int i0 = (tile / 25) * 4;
            const int j0 = (tile % 25) * 4;
            float acc[16];
            #pragma unroll
            for (int k = 0; k < 16; ++k) acc[k] = 0.f;
            #pragma unroll 4
            for (int p = 0; p < PP; ++p) {
                float4 u = *reinterpret_cast<const float4*>(Us + p * DD + i0);
                float4 v = *reinterpret_cast<const float4*>(Vs + p * DD + j0);
                acc[0]  += u.x * v.x; acc[1]  += u.x * v.y; acc[2]  += u.x * v.z; acc[3]  += u.x * v.w;
                acc[4]  += u.y * v.x; acc[5]  += u.y * v.y; acc[6]  += u.y * v.z; acc[7]  += u.y * v.w;
                acc[8]  += u.z * v.x; acc[9]  += u.z * v.y; acc[10] += u.z * v.z; acc[11] += u.z * v.w;
                acc[12] += u.w * v.x; acc[13] += u.w * v.y; acc[14] += u.w * v.z; acc[15] += u.w * v.w;
            }
            #pragma unroll
            for (int k = 0; k < 16; ++k) {
                tv[it * 16 + k] = acc[k];
                mx = fmaxf(mx, acc[k]);
            }
        }
    }
    #pragma unroll
    for (int off = 16; off; off >>= 1)
        mx = fmaxf(mx, __shfl_down_sync(0xffffffffu, mx, off));
    if ((tid & 31) == 0) red[tid >> 5] = mx;
    __syncthreads();
    if (tid == 0) {
        float t = red[0];
        #pragma unroll
        for (int w = 1; w < 8; ++w) t = fmaxf(t, red[w]);
        red[0] = t;
    }
    __syncthreads();
    const float inv = 1.f / red[0];

    float* outp = g_imgs + m * (DD * DD);
    #pragma unroll
    for (int it = 0; it < 3; ++it) {
        const int tile = tid + it * 256;
        if (tile < 625) {
            const int i0 = (tile / 25) * 4;
            const int j0 = (tile % 25) * 4;
            #pragma unroll
            for (int a = 0; a < 4; ++a)
                #pragma unroll
                for (int c = 0; c < 4; ++c)
                    outp[(i0 + a) * DD + (j0 + c)] = tv[it * 16 + a * 4 + c] * inv;
        }
    }
}

// ============= K3: conv1 (R4-proven scalar) =================================
template<int IC, int W, int OC_BLOCK, int PR, int SEL>
__global__ __launch_bounds__(224, 2) void conv_pool_kernel(
    const float* __restrict__ wts, const float* __restrict__ bias)
{
    constexpr int OPT = 4;
    constexpr int TR  = 2 * PR + 4;
    constexpr int WP  = W + 4;
    constexpr int PC  = W / 2;
    constexpr int NOCQ = OC_BLOCK / OPT;
    const float* in  = (SEL == 0) ? g_imgs : g_y1;
    float*       out = (SEL == 0) ? g_y1   : g_y2;
    const int total_oc = (SEL == 0) ? 16 : 32;

    extern __shared__ float smc[];
    float* tile = smc;
    float* wsm  = tile + IC * TR * WP;
    float* bsm  = wsm + OC_BLOCK * IC * 28;

    const int img = blockIdx.x, rg = blockIdx.y, ocg = blockIdx.z;
    const int prStart = rg * PR;
    const int ocStart = ocg * OC_BLOCK;
    const int tid = threadIdx.x;

    for (int idx = tid; idx < OC_BLOCK * IC * 28; idx += blockDim.x) {
        const int oc = idx / (IC * 28);
        const int r  = idx % (IC * 28);
        const int ic = r / 28, k = r % 28;
        wsm[idx] = (k < 25) ? wts[((ocStart + oc) * IC + ic) * 25 + k] : 0.f;
    }
    if (tid < OC_BLOCK) bsm[tid] = bias[ocStart + tid];

    const int y0 = prStart * 2 - 2;
    for (int idx = tid; idx < IC * TR * WP; idx += blockDim.x) {
        const int ic = idx / (TR * WP);
        const int r  = (idx / WP) % TR;
        const int c  = idx % WP;
        const int y = y0 + r, xx = c - 2;
        float v = 0.f;
        if (y >= 0 && y < W && xx >= 0 && xx < W)
            v = in[((img * IC + ic) * W + y) * W + xx];
        tile[idx] = v;
    }
    __syncthreads();

    const int nPos = PR * PC * NOCQ;
    for (int pos = tid; pos < nPos; pos += blockDim.x) {
        const int sp  = pos % (PR * PC);
        const int ocq = pos / (PR * PC);
        const int pr = sp / PC, pc = sp % PC;
        if (prStart + pr >= PC) continue;
        const int ty = 2 * pr, tx = 2 * pc;

        float acc[OPT][4];
        #pragma unroll
        for (int o = 0; o < OPT; ++o)
            acc[o][0] = acc[o][1] = acc[o][2] = acc[o][3] = 0.f;

        #pragma unroll 1
        for (int ic = 0; ic < IC; ++ic) {
            float patch[6][6];
            const float* tp = tile + (ic * TR + ty) * WP + tx;
            #pragma unroll
            for (int r = 0; r < 6; ++r) {
                float2 a = *reinterpret_cast<const float2*>(tp + r * WP);
                float2 bq = *reinterpret_cast<const float2*>(tp + r * WP + 2);
                float2 c = *reinterpret_cast<const float2*>(tp + r * WP + 4);
                patch[r][0] = a.x;  patch[r][1] = a.y;
                patch[r][2] = bq.x; patch[r][3] = bq.y;
                patch[r][4] = c.x;  patch[r][5] = c.y;
            }
            #pragma unroll
            for (int o = 0; o < OPT; ++o) {
                const float4* w4 = reinterpret_cast<const float4*>(
                    wsm + ((ocq * OPT + o) * IC + ic) * 28);
                float wv[28];
                #pragma unroll
                for (int q = 0; q < 7; ++q)
                    *reinterpret_cast<float4*>(wv + 4 * q) = w4[q];
                #pragma unroll
                for (int ky = 0; ky < 5; ++ky)
                    #pragma unroll
                    for (int kx = 0; kx < 5; ++kx) {
                        const float wgt = wv[ky * 5 + kx];
                        acc[o][0] += patch[ky][kx]         * wgt;
                        acc[o][1] += patch[ky][kx + 1]     * wgt;
                        acc[o][2] += patch[ky + 1][kx]     * wgt;
                        acc[o][3] += patch[ky + 1][kx + 1] * wgt;
                    }
            }
        }
        #pragma unroll
        for (int o = 0; o < OPT; ++o) {
            const int oc = ocStart + ocq * OPT + o;
            float mv = fmaxf(fmaxf(acc[o][0], acc[o][1]),
                             fmaxf(acc[o][2], acc[o][3])) + bsm[ocq * OPT + o];
            mv = fmaxf(mv, 0.f);
            out[((img * total_oc + oc) * PC + (prStart + pr)) * PC + pc] = mv;
        }
    }
}

// ============= K4: conv2 as tf32 mma.sync implicit GEMM =====================
// 3 pooled rows per CTA -> grid 32x9 = 288 CTAs = one balanced wave at
// 2 CTAs/SM. M = 300 conv positions (19 m-tiles), N = 32, K = 400.
__device__ __forceinline__ uint32_t to_tf32(float x) {
    uint32_t r;
    asm("cvt.rna.tf32.f32 %0, %1;" : "=r"(r) : "f"(x));
    return r;
}
__device__ __forceinline__ void mma_tf32(
    float* d, const uint32_t* a, const uint32_t* b)
{
    asm volatile(
        "mma.sync.aligned.m16n8k8.row.col.f32.tf32.tf32.f32 "
        "{%0,%1,%2,%3}, {%4,%5,%6,%7}, {%8,%9}, {%0,%1,%2,%3};\n"
        : "+f"(d[0]), "+f"(d[1]), "+f"(d[2]), "+f"(d[3])
        : "r"(a[0]), "r"(a[1]), "r"(a[2]), "r"(a[3]),
          "r"(b[0]), "r"(b[1]));
}

#define C2_TR   10
#define C2_TILE (16 * C2_TR * 57)                      // 9120
#define C2_SMEM_FLOATS (C2_TILE + 50 * 32 * 8 + 400 + 32)   // 22352
__global__ __launch_bounds__(256, 2) void conv2_tc_kernel(
    const float* __restrict__ wts, const float* __restrict__ bias)
{
    extern __shared__ float s[];
    float* tile = s;                          // [16][10][57]
    float* Bf   = tile + C2_TILE;             // [50][32][8]
    int*   offs = (int*)(Bf + 50 * 32 * 8);   // [400]
    float* bsm  = (float*)(offs + 400);       // [32]
    float* Cs   = s;                          // [304][33] alias (post-mainloop)

    const int img = blockIdx.x;
    const int rg  = blockIdx.y;               // 3-pooled-row group (0..8)
    const int tid = threadIdx.x;
    const int lane = tid & 31, warp = tid >> 5;
    const int grp = lane >> 2, qid = lane & 3;

    // B fragments: Bf[ks][lane][2*nt+h] = tf32(w[n=grp+8nt][k=8ks+qid+4h])
    for (int idx = tid; idx < 50 * 32; idx += 256) {
        const int ks = idx >> 5, ln = idx & 31;
        const int g2 = ln >> 2, q2 = ln & 3;
        float v[8];
        #pragma unroll
        for (int nt = 0; nt < 4; ++nt) {
            const float* wp = wts + (g2 + 8 * nt) * 400 + 8 * ks + q2;
            v[2 * nt]     = __uint_as_float(to_tf32(wp[0]));
            v[2 * nt + 1] = __uint_as_float(to_tf32(wp[4]));
        }
        float* dst = Bf + idx * 8;
        *reinterpret_cast<float4*>(dst)     = *reinterpret_cast<float4*>(v);
        *reinterpret_cast<float4*>(dst + 4) = *reinterpret_cast<float4*>(v + 4);
    }
    if (tid < 32) bsm[tid] = bias[tid];
    for (int k = tid; k < 400; k += 256) {
        int ic = k / 25, kk = k % 25;
        offs[k] = ic * (C2_TR * 57) + (kk / 5) * 57 + (kk % 5);
    }
    // input tile: rows iy0..iy0+9 (halo for 6 conv rows)
    const int iy0 = 6 * rg - 2;
    for (int i = tid; i < C2_TILE; i += 256) {
        int ic = i / (C2_TR * 57), r = (i / 57) % C2_TR, c = i % 57;
        int iy = iy0 + r, ix = c - 2;
        float v = 0.f;
        if (iy >= 0 && iy < 50 && ix >= 0 && ix < 50)
            v = g_y1[((img * 16 + ic) * 50 + iy) * 50 + ix];
        tile[i] = __uint_as_float(to_tf32(v));
    }
    __syncthreads();

    // A row base addrs for up to 3 m-tiles: mt = warp + 8t
    int abase[3][2];
    int nvalid = 0;
    #pragma unroll
    for (int t = 0; t < 3; ++t) {
        const int mt = warp + 8 * t;
        if (mt < 19) nvalid = t + 1;
        #pragma unroll
        for (int h = 0; h < 2; ++h) {
            int m = mt * 16 + grp + h * 8;
            if (m > 299) m = 299;
            abase[t][h] = (m / 50) * 57 + (m % 50);
        }
    }

    float acc[3][4][4];
    #pragma unroll
    for (int t = 0; t < 3; ++t)
        #pragma unroll
        for (int nt = 0; nt < 4; ++nt)
            acc[t][nt][0] = acc[t][nt][1] = acc[t][nt][2] = acc[t][nt][3] = 0.f;

    #pragma unroll 2
    for (int ks = 0; ks < 50; ++ks) {
        const int o0 = offs[ks * 8 + qid];
        const int o1 = offs[ks * 8 + qid + 4];

        const float4* bp = reinterpret_cast<const float4*>(
            Bf + (ks * 32 + lane) * 8);
        float4 bv0 = bp[0], bv1 = bp[1];
        uint32_t b[4][2];
        b[0][0] = __float_as_uint(bv0.x); b[0][1] = __float_as_uint(bv0.y);
        b[1][0] = __float_as_uint(bv0.z); b[1][1] = __float_as_uint(bv0.w);
        b[2][0] = __float_as_uint(bv1.x); b[2][1] = __float_as_uint(bv1.y);
        b[3][0] = __float_as_uint(bv1.z); b[3][1] = __float_as_uint(bv1.w);

        #pragma unroll
        for (int t = 0; t < 3; ++t) {
            if (t < nvalid) {
                uint32_t a[4];
                a[0] = __float_as_uint(tile[abase[t][0] + o0]);
                a[1] = __float_as_uint(tile[abase[t][1] + o0]);
                a[2] = __float_as_uint(tile[abase[t][0] + o1]);
                a[3] = __float_as_uint(tile[abase[t][1] + o1]);
                #pragma unroll
                for (int nt = 0; nt < 4; ++nt)
                    mma_tf32(acc[t][nt], a, b[nt]);
            }
        }
    }

    __syncthreads();   // tile/Bf reads done; Cs may overwrite

    #pragma unroll
    for (int t = 0; t < 3; ++t) {
        const int mt = warp + 8 * t;
        if (mt < 19) {
            const int m0 = mt * 16 + grp;
            #pragma unroll
            for (int nt = 0; nt < 4; ++nt) {
                const int n0 = nt * 8 + 2 * qid;
                Cs[m0 * 33 + n0]           = acc[t][nt][0];
                Cs[m0 * 33 + n0 + 1]       = acc[t][nt][1];
                Cs[(m0 + 8) * 33 + n0]     = acc[t][nt][2];
                Cs[(m0 + 8) * 33 + n0 + 1] = acc[t][nt][3];
            }
        }
    }
    __syncthreads();

    // fused bias + 2x2 maxpool + relu : 3 pooled rows x 25 x 32 oc
    for (int idx = tid; idx < 2400; idx += 256) {
        const int oc = idx & 31;
        const int pc = (idx >> 5) % 25;
        const int prl = idx / 800;             // 0..2
        const int prow = 3 * rg + prl;
        if (prow < 25) {
            const int m00 = 2 * prl * 50 + 2 * pc;
            float v = fmaxf(fmaxf(Cs[m00 * 33 + oc],        Cs[(m00 + 1) * 33 + oc]),
                            fmaxf(Cs[(m00 + 50) * 33 + oc], Cs[(m00 + 51) * 33 + oc]));
            v = fmaxf(v + bsm[oc], 0.f);
            g_y2[((img * 32 + oc) * 25 + prow) * 25 + pc] = v;
        }
    }
}

// ======================= K5: FC head ========================================
__global__ __launch_bounds__(256) void fc_kernel(
    const float* __restrict__ w, const float* __restrict__ b,
    float* __restrict__ out)
{
    const int bc = blockIdx.x;
    const int bi = bc / NCLS, c = bc % NCLS;
    const float4* yb = reinterpret_cast<const float4*>(g_y2 + bi * 20000);
    const float4* wc = reinterpret_cast<const float4*>(w + c * 20000);
    float s = 0.f;
    for (int k = threadIdx.x; k < 5000; k += 256) {
        float4 a = yb[k], ww = wc[k];
        s += a.x * ww.x + a.y * ww.y + a.z * ww.z + a.w * ww.w;
    }
    #pragma unroll
    for (int off = 16; off; off >>= 1)
        s += __shfl_down_sync(0xffffffffu, s, off);
    __shared__ float red[8];
    if ((threadIdx.x & 31) == 0) red[threadIdx.x >> 5] = s;
    __syncthreads();
    if (threadIdx.x == 0) {
        float t = 0.f;
        #pragma unroll
        for (int wi = 0; wi < 8; ++wi) t += red[wi];
        out[bi * NCLS + c] = t + b[c];
    }
}

// ============================== launch ======================================
extern "C" void kernel_launch(void* const* d_in, const int* in_sizes, int n_in,
                              void* d_out, int out_size)
{
    const float* x        = (const float*)d_in[0];
    const int*   pidx0    = (const int*)  d_in[1];
    const int*   pidx1    = (const int*)  d_in[2];
    const float* w1       = (const float*)d_in[3];
    const float* b1       = (const float*)d_in[4];
    const float* w2       = (const float*)d_in[5];
    const float* b2       = (const float*)d_in[6];
    const float* conv1_w  = (const float*)d_in[7];
    const float* conv1_b  = (const float*)d_in[8];
    const float* conv2_w  = (const float*)d_in[9];
    const float* conv2_b  = (const float*)d_in[10];
    const float* out_w    = (const float*)d_in[11];
    const float* out_b    = (const float*)d_in[12];
    float* out = (float*)d_out;

    const int pers_smem  = PERS_SMEM_FLOATS * 4;                      // 103552
    const int conv1_smem = (2 * 8 * 104 + 16 * 2 * 28 + 16) * 4;     // 10304
    const int conv2_smem = C2_SMEM_FLOATS * 4;                        // 89408

    cudaFuncSetAttribute(pers_image_kernel,
        cudaFuncAttributeMaxDynamicSharedMemorySize, pers_smem);
    cudaFuncSetAttribute(conv2_tc_kernel,
        cudaFuncAttributeMaxDynamicSharedMemorySize, conv2_smem);

    // K1: node filtration -> g_filt and d_out[320:]
    filt_kernel<<<250, 256>>>(x, w1, b1, w2, b2, out + BB * NCLS);

    // K2: persistence images -> g_imgs [B,2,100,100]
    pers_image_kernel<<<64, 256, pers_smem>>>(pidx0, pidx1);

    // K3: conv1 + relu + pool  [B,2,100,100] -> [B,16,50,50]
    conv_pool_kernel<2, 100, 16, 2, 0><<<dim3(32, 25, 1), 224, conv1_smem>>>(
        conv1_w, conv1_b);

    // K4: conv2 via tf32 tensor cores, one balanced wave (288 CTAs)
    conv2_tc_kernel<<<dim3(32, 9), 256, conv2_smem>>>(conv2_w, conv2_b);

    // K5: FC -> d_out[0:320]
    fc_kernel<<<BB * NCLS, 256>>>(out_w, out_b, out);
}

// round 10
// speedup vs baseline: 1.5576x; 1.0184x over previous
#include <cuda_runtime.h>
#include <cstdint>

#define NN     16000
#define IN_DIM 128
#define HID    64
#define BB     32
#define PP     128
#define DD     100
#define NCLS   10
#define INV_PI 0.31830988618379067f

// ---------------- scratch (device globals; no allocation allowed) -----------
__device__ float    g_filt[NN];
__device__ float    g_imgs[BB * 2 * DD * DD];    // UNNORMALIZED pers images
__device__ unsigned g_immax[BB * 2];             // per image-channel max (fp bits)
__device__ float    g_y1[BB * 16 * 50 * 50];
__device__ float    g_y2[BB * 32 * 25 * 25];

// ======================= K1: node filtration MLP ============================
__global__ __launch_bounds__(256) void filt_kernel(
    const float* __restrict__ x, const float* __restrict__ w1,
    const float* __restrict__ b1, const float* __restrict__ w2,
    const float* __restrict__ b2, float* __restrict__ out_filt)
{
    const int tid   = threadIdx.x;
    if (blockIdx.x == 0 && tid < BB * 2) g_immax[tid] = 0u;  // reset maxes
    const int j     = tid & 63;
    const int chunk = tid >> 6;

    float wr[32];
    #pragma unroll
    for (int k = 0; k < 32; ++k)
        wr[k] = w1[(chunk * 32 + k) * HID + j];
    const float b1j = b1[j];
    const float w2j = w2[j];
    const float b2v = b2[0];

    __shared__ float xs[4][IN_DIM];
    __shared__ float part[4][4 * 64];
    __shared__ float nsum[4][2];

    for (int grp = 0; grp < 16; ++grp) {
        const int nbase = blockIdx.x * 64 + grp * 4;
        __syncthreads();
        for (int idx = tid; idx < 4 * IN_DIM; idx += 256) {
            int n = idx >> 7, c = idx & 127;
            xs[n][c] = x[(nbase + n) * IN_DIM + c];
        }
        __syncthreads();

        #pragma unroll
        for (int n = 0; n < 4; ++n) {
            const float4* xp = reinterpret_cast<const float4*>(xs[n] + chunk * 32);
            float s = 0.f;
            #pragma unroll
            for (int q = 0; q < 8; ++q) {
                float4 v = xp[q];
                s += v.x * wr[4 * q] + v.y * wr[4 * q + 1]
                   + v.z * wr[4 * q + 2] + v.w * wr[4 * q + 3];
            }
            part[n][chunk * 64 + j] = s;
        }
        __syncthreads();

        {
            const int n2 = chunk;
            float v = part[n2][j] + part[n2][64 + j]
                    + part[n2][128 + j] + part[n2][192 + j] + b1j;
            float h = fmaxf(v, 0.f) * w2j;
            #pragma unroll
            for (int off = 16; off; off >>= 1)
                h += __shfl_down_sync(0xffffffffu, h, off);
            if ((j & 31) == 0) nsum[n2][j >> 5] = h;
        }
        __syncthreads();
        if (tid < 4) {
            const int node = nbase + tid;
            float t = nsum[tid][0] + nsum[tid][1] + b2v;
            float f = 1.f / (1.f + __expf(-t));
            g_filt[node]   = f;
            out_filt[node] = f;
        }
    }
}

// ================ K2: persistence image (quarter blocks, atomic max) ========
// 256 blocks: m = (imgch<<2)|q. Each block computes an i-quarter of one
// image-channel, writes UNNORMALIZED values, atomicMax's per-imgch max.
// Normalization is fused into conv1's tile load (conv linear pre-bias).
#define P_UW 28
#define PERS_SMEM_FLOATS (PP * P_UW + PP * DD + PP + PP + 32)
__global__ __launch_bounds__(256) void pers_image_kernel(
    const int* __restrict__ pidx0, const int* __restrict__ pidx1)
{
    extern __shared__ float sm[];
    float* Us = sm;                 // [128][28]
    float* Vs = Us + PP * P_UW;     // [128][100]
    float* bs = Vs + PP * DD;
    float* ps = bs + PP;
    float* red = ps + PP;

    const int m     = blockIdx.x;
    const int imgch = m >> 2;
    const int q     = m & 3;
    const int b  = imgch >> 1;
    const int ch = imgch & 1;
    const int* pidx = ch ? pidx1 : pidx0;
    const int tid = threadIdx.x;

    const int itile0  = (q == 0) ? 0 : (7 + 6 * (q - 1));   // 0,7,13,19
    const int ntilesI = (q == 0) ? 7 : 6;
    const int ibase   = itile0 * 4;
    const int iwidth  = ntilesI * 4;                        // 28 or 24

    if (tid < PP) {
        int i0 = pidx[(b * PP + tid) * 2 + 0];
        int i1 = pidx[(b * PP + tid) * 2 + 1];
        float birth = g_filt[i0];
        bs[tid] = birth;
        ps[tid] = g_filt[i1] - birth;
    }
    __syncthreads();

    for (int idx = tid; idx < PP * P_UW; idx += 256) {
        int p = idx / P_UW, t = idx % P_UW;
        float c  = (float)(ibase + t) * 0.01f;
        float db = bs[p] - c;
        Us[idx] = (t < iwidth) ? __expf(-db * db) : 0.f;
    }
    for (int idx = tid; idx < PP * DD; idx += 256) {
        int p = idx / DD, t = idx % DD;
        float c  = (float)t * 0.01f;
        float dp = ps[p] - c;
        Vs[idx] = INV_PI * __expf(-dp * dp);
    }
    __syncthreads();

    const int nt = ntilesI * 25;       // 175 or 150, <= 256: one tile/thread
    float acc[16];
    float mx = 0.f;
    int i0 = 0, j0 = 0;
    if (tid < nt) {
        i0 = (tid / 25) * 4;           // local i
        j0 = (tid % 25) * 4;
        #pragma unroll
        for (int k = 0; k < 16; ++k) acc[k] = 0.f;
        #pragma unroll 4
        for (int p = 0; p < PP; ++p) {
            float4 u = *reinterpret_cast<const float4*>(Us + p * P_UW + i0);
            float4 v = *reinterpret_cast<const float4*>(Vs + p * DD + j0);
            acc[0]  += u.x * v.x; acc[1]  += u.x * v.y; acc[2]  += u.x * v.z; acc[3]  += u.x * v.w;
            acc[4]  += u.y * v.x; acc[5]  += u.y * v.y; acc[6]  += u.y * v.z; acc[7]  += u.y * v.w;
            acc[8]  += u.z * v.x; acc[9]  += u.z * v.y; acc[10] += u.z * v.z; acc[11] += u.z * v.w;
            acc[12] += u.w * v.x; acc[13] += u.w * v.y; acc[14] += u.w * v.z; acc[15] += u.w * v.w;
        }
        #pragma unroll
        for (int k = 0; k < 16; ++k) mx = fmaxf(mx, acc[k]);
    }
    // block max -> atomicMax (positive floats: bit compare works)
    #pragma unroll
    for (int off = 16; off; off >>= 1)
        mx = fmaxf(mx, __shfl_down_sync(0xffffffffu, mx, off));
    if ((tid & 31) == 0) red[tid >> 5] = mx;
    __syncthreads();
    if (tid == 0) {
        float t = red[0];
        #pragma unroll
        for (int w = 1; w < 8; ++w) t = fmaxf(t, red[w]);
        atomicMax(&g_immax[imgch], __float_as_uint(t));
    }

    if (tid < nt) {
        float* outp = g_imgs + imgch * (DD * DD);
        #pragma unroll
        for (int a = 0; a < 4; ++a)
            #pragma unroll
            for (int c = 0; c < 4; ++c)
                outp[(ibase + i0 + a) * DD + (j0 + c)] = acc[a * 4 + c];
    }
}

// ============= K3: conv1 (scalar) with fused per-channel normalization ======
template<int IC, int W, int OC_BLOCK, int PR, int SEL>
__global__ __launch_bounds__(224, 2) void conv_pool_kernel(
    const float* __restrict__ wts, const float* __restrict__ bias)
{
    constexpr int OPT = 4;
    constexpr int TR  = 2 * PR + 4;
    constexpr int WP  = W + 4;
    constexpr int PC  = W / 2;
    constexpr int NOCQ = OC_BLOCK / OPT;
    const float* in  = (SEL == 0) ? g_imgs : g_y1;
    float*       out = (SEL == 0) ? g_y1   : g_y2;
    const int total_oc = (SEL == 0) ? 16 : 32;

    extern __shared__ float smc[];
    float* tile = smc;
    float* wsm  = tile + IC * TR * WP;
    float* bsm  = wsm + OC_BLOCK * IC * 28;

    const int img = blockIdx.x, rg = blockIdx.y, ocg = blockIdx.z;
    const int prStart = rg * PR;
    const int ocStart = ocg * OC_BLOCK;
    const int tid = threadIdx.x;

    float inv[IC > 2 ? 1 : 2];
    if (SEL == 0) {
        inv[0] = 1.f / __uint_as_float(g_immax[img * 2]);
        inv[1] = 1.f / __uint_as_float(g_immax[img * 2 + 1]);
    }

    for (int idx = tid; idx < OC_BLOCK * IC * 28; idx += blockDim.x) {
        const int oc = idx / (IC * 28);
        const int r  = idx % (IC * 28);
        const int ic = r / 28, k = r % 28;
        wsm[idx] = (k < 25) ? wts[((ocStart + oc) * IC + ic) * 25 + k] : 0.f;
    }
    if (tid < OC_BLOCK) bsm[tid] = bias[ocStart + tid];

    const int y0 = prStart * 2 - 2;
    for (int idx = tid; idx < IC * TR * WP; idx += blockDim.x) {
        const int ic = idx / (TR * WP);
        const int r  = (idx / WP) % TR;
        const int c  = idx % WP;
        const int y = y0 + r, xx = c - 2;
        float v = 0.f;
        if (y >= 0 && y < W && xx >= 0 && xx < W)
            v = in[((img * IC + ic) * W + y) * W + xx];
        if (SEL == 0) v *= inv[ic & 1];
        tile[idx] = v;
    }
    __syncthreads();

    const int nPos = PR * PC * NOCQ;
    for (int pos = tid; pos < nPos; pos += blockDim.x) {
        const int sp  = pos % (PR * PC);
        const int ocq = pos / (PR * PC);
        const int pr = sp / PC, pc = sp % PC;
        if (prStart + pr >= PC) continue;
        const int ty = 2 * pr, tx = 2 * pc;

        float acc[OPT][4];
        #pragma unroll
        for (int o = 0; o < OPT; ++o)
            acc[o][0] = acc[o][1] = acc[o][2] = acc[o][3] = 0.f;

        #pragma unroll 1
        for (int ic = 0; ic < IC; ++ic) {
            float patch[6][6];
            const float* tp = tile + (ic * TR + ty) * WP + tx;
            #pragma unroll
            for (int r = 0; r < 6; ++r) {
                float2 a = *reinterpret_cast<const float2*>(tp + r * WP);
                float2 bq = *reinterpret_cast<const float2*>(tp + r * WP + 2);
                float2 c = *reinterpret_cast<const float2*>(tp + r * WP + 4);
                patch[r][0] = a.x;  patch[r][1] = a.y;
                patch[r][2] = bq.x; patch[r][3] = bq.y;
                patch[r][4] = c.x;  patch[r][5] = c.y;
            }
            #pragma unroll
            for (int o = 0; o < OPT; ++o) {
                const float4* w4 = reinterpret_cast<const float4*>(
                    wsm + ((ocq * OPT + o) * IC + ic) * 28);
                float wv[28];
                #pragma unroll
                for (int q = 0; q < 7; ++q)
                    *reinterpret_cast<float4*>(wv + 4 * q) = w4[q];
                #pragma unroll
                for (int ky = 0; ky < 5; ++ky)
                    #pragma unroll
                    for (int kx = 0; kx < 5; ++kx) {
                        const float wgt = wv[ky * 5 + kx];
                        acc[o][0] += patch[ky][kx]         * wgt;
                        acc[o][1] += patch[ky][kx + 1]     * wgt;
                        acc[o][2] += patch[ky + 1][kx]     * wgt;
                        acc[o][3] += patch[ky + 1][kx + 1] * wgt;
                    }
            }
        }
        #pragma unroll
        for (int o = 0; o < OPT; ++o) {
            const int oc = ocStart + ocq * OPT + o;
            float mv = fmaxf(fmaxf(acc[o][0], acc[o][1]),
                             fmaxf(acc[o][2], acc[o][3])) + bsm[ocq * OPT + o];
            mv = fmaxf(mv, 0.f);
            out[((img * total_oc + oc) * PC + (prStart + pr)) * PC + pc] = mv;
        }
    }
}

// ============= K4: conv2 tf32 mma.sync, tap-major K (no offset table) =======
// K order: k = tap*16 + ic. For thread qid: ic = qid + 8*(ks&1), tap = ks>>1.
// Offsets are pure ALU: o0 = ic*570 + tr*57 + tc, o1 = o0 + 2280.
__device__ __forceinline__ uint32_t to_tf32(float x) {
    uint32_t r;
    asm("cvt.rna.tf32.f32 %0, %1;" : "=r"(r) : "f"(x));
    return r;
}
__device__ __forceinline__ void mma_tf32(
    float* d, const uint32_t* a, const uint32_t* b)
{
    asm volatile(
        "mma.sync.aligned.m16n8k8.row.col.f32.tf32.tf32.f32 "
        "{%0,%1,%2,%3}, {%4,%5,%6,%7}, {%8,%9}, {%0,%1,%2,%3};\n"
        : "+f"(d[0]), "+f"(d[1]), "+f"(d[2]), "+f"(d[3])
        : "r"(a[0]), "r"(a[1]), "r"(a[2]), "r"(a[3]),
          "r"(b[0]), "r"(b[1]));
}

#define C2_TR   10
#define C2_TILE (16 * C2_TR * 57)                        // 9120
#define C2_SMEM_FLOATS (C2_TILE + 50 * 32 * 8 + 32)      // 21952
__global__ __launch_bounds__(256, 2) void conv2_tc_kernel(
    const float* __restrict__ wts, const float* __restrict__ bias)
{
    extern __shared__ float s[];
    float* tile = s;                          // [16][10][57]
    float* Bf   = tile + C2_TILE;             // [50][32][8]
    float* bsm  = Bf + 50 * 32 * 8;           // [32]
    float* Cs   = s;                          // [304][33] alias (post-mainloop)

    const int img = blockIdx.x;
    const int rg  = blockIdx.y;               // 3-pooled-row group (0..8)
    const int tid = threadIdx.x;
    const int lane = tid & 31, warp = tid >> 5;
    const int grp = lane >> 2, qid = lane & 3;

    // B fragments in tap-major k-order:
    // Bf[ks][lane][2nt+h] = tf32(w[n=g2+8nt][k_lin=8ks+q2+4h]),
    //   k_lin -> tap = k_lin>>4, ic = k_lin&15, w = wts[n*400 + ic*25 + tap]
    for (int idx = tid; idx < 50 * 32; idx += 256) {
        const int ks = idx >> 5, ln = idx & 31;
        const int g2 = ln >> 2, q2 = ln & 3;
        float v[8];
        #pragma unroll
        for (int nt = 0; nt < 4; ++nt) {
            #pragma unroll
            for (int h = 0; h < 2; ++h) {
                const int kl  = 8 * ks + q2 + 4 * h;
                const int tap = kl >> 4, ic = kl & 15;
                v[2 * nt + h] = __uint_as_float(
                    to_tf32(wts[(g2 + 8 * nt) * 400 + ic * 25 + tap]));
            }
        }
        float* dst = Bf + idx * 8;
        *reinterpret_cast<float4*>(dst)     = *reinterpret_cast<float4*>(v);
        *reinterpret_cast<float4*>(dst + 4) = *reinterpret_cast<float4*>(v + 4);
    }
    if (tid < 32) bsm[tid] = bias[tid];

    // input tile rows iy0..iy0+9 (halo for 6 conv rows)
    const int iy0 = 6 * rg - 2;
    for (int i = tid; i < C2_TILE; i += 256) {
        int ic = i / (C2_TR * 57), r = (i / 57) % C2_TR, c = i % 57;
        int iy = iy0 + r, ix = c - 2;
        float v = 0.f;
        if (iy >= 0 && iy < 50 && ix >= 0 && ix < 50)
            v = g_y1[((img * 16 + ic) * 50 + iy) * 50 + ix];
        tile[i] = __uint_as_float(to_tf32(v));
    }
    __syncthreads();

    int abase[3][2];
    int nvalid = 0;
    #pragma unroll
    for (int t = 0; t < 3; ++t) {
        const int mt = warp + 8 * t;
        if (mt < 19) nvalid = t + 1;
        #pragma unroll
        for (int h = 0; h < 2; ++h) {
            int m = mt * 16 + grp + h * 8;
            if (m > 299) m = 299;
            abase[t][h] = (m / 50) * 57 + (m % 50);
        }
    }

    float acc[3][4][4];
    #pragma unroll
    for (int t = 0; t < 3; ++t)
        #pragma unroll
        for (int nt = 0; nt < 4; ++nt)
            acc[t][nt][0] = acc[t][nt][1] = acc[t][nt][2] = acc[t][nt][3] = 0.f;

    const int ic0 = qid * 570;          // ks even: ic = qid
    const int ic1 = (qid + 8) * 570;    // ks odd : ic = qid+8
    int tr = 0, tc = 0;                 // tap = ks>>1 tracked incrementally

    #pragma unroll 2
    for (int ks = 0; ks < 50; ++ks) {
        const int tOff = tr * 57 + tc;
        const int o0 = ((ks & 1) ? ic1 : ic0) + tOff;
        const int o1 = o0 + 2280;       // ic+4

        const float4* bp = reinterpret_cast<const float4*>(
            Bf + (ks * 32 + lane) * 8);
        float4 bv0 = bp[0], bv1 = bp[1];
        uint32_t b[4][2];
        b[0][0] = __float_as_uint(bv0.x); b[0][1] = __float_as_uint(bv0.y);
        b[1][0] = __float_as_uint(bv0.z); b[1][1] = __float_as_uint(bv0.w);
        b[2][0] = __float_as_uint(bv1.x); b[2][1] = __float_as_uint(bv1.y);
        b[3][0] = __float_as_uint(bv1.z); b[3][1] = __float_as_uint(bv1.w);

        #pragma unroll
        for (int t = 0; t < 3; ++t) {
            if (t < nvalid) {
                uint32_t a[4];
                a[0] = __float_as_uint(tile[abase[t][0] + o0]);
                a[1] = __float_as_uint(tile[abase[t][1] + o0]);
                a[2] = __float_as_uint(tile[abase[t][0] + o1]);
                a[3] = __float_as_uint(tile[abase[t][1] + o1]);
                #pragma unroll
                for (int nt = 0; nt < 4; ++nt)
                    mma_tf32(acc[t][nt], a, b[nt]);
            }
        }
        if (ks & 1) { if (++tc == 5) { tc = 0; ++tr; } }
    }

    __syncthreads();   // tile/Bf reads done; Cs may overwrite

    #pragma unroll
    for (int t = 0; t < 3; ++t) {
        const int mt = warp + 8 * t;
        if (mt < 19) {
            const int m0 = mt * 16 + grp;
            #pragma unroll
            for (int nt = 0; nt < 4; ++nt) {
                const int n0 = nt * 8 + 2 * qid;
                Cs[m0 * 33 + n0]           = acc[t][nt][0];
                Cs[m0 * 33 + n0 + 1]       = acc[t][nt][1];
                Cs[(m0 + 8) * 33 + n0]     = acc[t][nt][2];
                Cs[(m0 + 8) * 33 + n0 + 1] = acc[t][nt][3];
            }
        }
    }
    __syncthreads();

    for (int idx = tid; idx < 2400; idx += 256) {
        const int oc = idx & 31;
        const int pc = (idx >> 5) % 25;
        const int prl = idx / 800;
        const int prow = 3 * rg + prl;
        if (prow < 25) {
            const int m00 = 2 * prl * 50 + 2 * pc;
            float v = fmaxf(fmaxf(Cs[m00 * 33 + oc],        Cs[(m00 + 1) * 33 + oc]),
                            fmaxf(Cs[(m00 + 50) * 33 + oc], Cs[(m00 + 51) * 33 + oc]));
            v = fmaxf(v + bsm[oc], 0.f);
            g_y2[((img * 32 + oc) * 25 + prow) * 25 + pc] = v;
        }
    }
}

// ======================= K5: FC head ========================================
__global__ __launch_bounds__(256) void fc_kernel(
    const float* __restrict__ w, const float* __restrict__ b,
    float* __restrict__ out)
{
    const int bc = blockIdx.x;
    const int bi = bc / NCLS, c = bc % NCLS;
    const float4* yb = reinterpret_cast<const float4*>(g_y2 + bi * 20000);
    const float4* wc = reinterpret_cast<const float4*>(w + c * 20000);
    float s = 0.f;
    for (int k = threadIdx.x; k < 5000; k += 256) {
        float4 a = yb[k], ww = wc[k];
        s += a.x * ww.x + a.y * ww.y + a.z * ww.z + a.w * ww.w;
    }
    #pragma unroll
    for (int off = 16; off; off >>= 1)
        s += __shfl_down_sync(0xffffffffu, s, off);
    __shared__ float red[8];
    if ((threadIdx.x & 31) == 0) red[threadIdx.x >> 5] = s;
    __syncthreads();
    if (threadIdx.x == 0) {
        float t = 0.f;
        #pragma unroll
        for (int wi = 0; wi < 8; ++wi) t += red[wi];
        out[bi * NCLS + c] = t + b[c];
    }
}

// ============================== launch ======================================
extern "C" void kernel_launch(void* const* d_in, const int* in_sizes, int n_in,
                              void* d_out, int out_size)
{
    const float* x        = (const float*)d_in[0];
    const int*   pidx0    = (const int*)  d_in[1];
    const int*   pidx1    = (const int*)  d_in[2];
    const float* w1       = (const float*)d_in[3];
    const float* b1       = (const float*)d_in[4];
    const float* w2       = (const float*)d_in[5];
    const float* b2       = (const float*)d_in[6];
    const float* conv1_w  = (const float*)d_in[7];
    const float* conv1_b  = (const float*)d_in[8];
    const float* conv2_w  = (const float*)d_in[9];
    const float* conv2_b  = (const float*)d_in[10];
    const float* out_w    = (const float*)d_in[11];
    const float* out_b    = (const float*)d_in[12];
    float* out = (float*)d_out;

    const int pers_smem  = PERS_SMEM_FLOATS * 4;                      // 66816
    const int conv1_smem = (2 * 8 * 104 + 16 * 2 * 28 + 16) * 4;     // 10304
    const int conv2_smem = C2_SMEM_FLOATS * 4;                        // 87808

    cudaFuncSetAttribute(pers_image_kernel,
        cudaFuncAttributeMaxDynamicSharedMemorySize, pers_smem);
    cudaFuncSetAttribute(conv2_tc_kernel,
        cudaFuncAttributeMaxDynamicSharedMemorySize, conv2_smem);

    // K1: node filtration -> g_filt and d_out[320:]  (also resets g_immax)
    filt_kernel<<<250, 256>>>(x, w1, b1, w2, b2, out + BB * NCLS);

    // K2: persistence images (unnormalized) + per-imgch max, 256 blocks
    pers_image_kernel<<<256, 256, pers_smem>>>(pidx0, pidx1);

    // K3: conv1 (+fused normalization) [B,2,100,100] -> [B,16,50,50]
    conv_pool_kernel<2, 100, 16, 2, 0><<<dim3(32, 25, 1), 224, conv1_smem>>>(
        conv1_w, conv1_b);

    // K4: conv2 via tf32 tensor cores, one balanced wave (288 CTAs)
    conv2_tc_kernel<<<dim3(32, 9), 256, conv2_smem>>>(conv2_w, conv2_b);

    // K5: FC -> d_out[0:320]
    fc_kernel<<<BB * NCLS, 256>>>(out_w, out_b, out);
}

// round 11
// speedup vs baseline: 1.5893x; 1.0204x over previous
#include <cuda_runtime.h>
#include <cstdint>

#define NN     16000
#define IN_DIM 128
#define HID    64
#define BB     32
#define PP     128
#define DD     100
#define NCLS   10
#define INV_PI 0.31830988618379067f

// ---------------- scratch (device globals; no allocation allowed) -----------
__device__ float    g_filt[NN];
__device__ float    g_imgs[BB * 2 * DD * DD];    // UNNORMALIZED pers images
__device__ unsigned g_immax[BB * 2];             // per image-channel max (fp bits)
__device__ float    g_y1[BB * 16 * 50 * 50];
__device__ float    g_y2[BB * 32 * 25 * 25];

// ======================= K1: node filtration MLP ============================
__global__ __launch_bounds__(256) void filt_kernel(
    const float* __restrict__ x, const float* __restrict__ w1,
    const float* __restrict__ b1, const float* __restrict__ w2,
    const float* __restrict__ b2, float* __restrict__ out_filt)
{
    const int tid   = threadIdx.x;
    if (blockIdx.x == 0 && tid < BB * 2) g_immax[tid] = 0u;  // reset maxes
    const int j     = tid & 63;
    const int chunk = tid >> 6;

    float wr[32];
    #pragma unroll
    for (int k = 0; k < 32; ++k)
        wr[k] = w1[(chunk * 32 + k) * HID + j];
    const float b1j = b1[j];
    const float w2j = w2[j];
    const float b2v = b2[0];

    __shared__ float xs[4][IN_DIM];
    __shared__ float part[4][4 * 64];
    __shared__ float nsum[4][2];

    for (int grp = 0; grp < 16; ++grp) {
        const int nbase = blockIdx.x * 64 + grp * 4;
        __syncthreads();
        for (int idx = tid; idx < 4 * IN_DIM; idx += 256) {
            int n = idx >> 7, c = idx & 127;
            xs[n][c] = x[(nbase + n) * IN_DIM + c];
        }
        __syncthreads();

        #pragma unroll
        for (int n = 0; n < 4; ++n) {
            const float4* xp = reinterpret_cast<const float4*>(xs[n] + chunk * 32);
            float s = 0.f;
            #pragma unroll
            for (int q = 0; q < 8; ++q) {
                float4 v = xp[q];
                s += v.x * wr[4 * q] + v.y * wr[4 * q + 1]
                   + v.z * wr[4 * q + 2] + v.w * wr[4 * q + 3];
            }
            part[n][chunk * 64 + j] = s;
        }
        __syncthreads();

        {
            const int n2 = chunk;
            float v = part[n2][j] + part[n2][64 + j]
                    + part[n2][128 + j] + part[n2][192 + j] + b1j;
            float h = fmaxf(v, 0.f) * w2j;
            #pragma unroll
            for (int off = 16; off; off >>= 1)
                h += __shfl_down_sync(0xffffffffu, h, off);
            if ((j & 31) == 0) nsum[n2][j >> 5] = h;
        }
        __syncthreads();
        if (tid < 4) {
            const int node = nbase + tid;
            float t = nsum[tid][0] + nsum[tid][1] + b2v;
            float f = 1.f / (1.f + __expf(-t));
            g_filt[node]   = f;
            out_filt[node] = f;
        }
    }
}

// ================ K2: persistence image (quarter blocks, atomic max) ========
#define P_UW 28
#define PERS_SMEM_FLOATS (PP * P_UW + PP * DD + PP + PP + 32)
__global__ __launch_bounds__(256) void pers_image_kernel(
    const int* __restrict__ pidx0, const int* __restrict__ pidx1)
{
    extern __shared__ float sm[];
    float* Us = sm;                 // [128][28]
    float* Vs = Us + PP * P_UW;     // [128][100]
    float* bs = Vs + PP * DD;
    float* ps = bs + PP;
    float* red = ps + PP;

    const int m     = blockIdx.x;
    const int imgch = m >> 2;
    const int q     = m & 3;
    const int b  = imgch >> 1;
    const int ch = imgch & 1;
    const int* pidx = ch ? pidx1 : pidx0;
    const int tid = threadIdx.x;

    const int itile0  = (q == 0) ? 0 : (7 + 6 * (q - 1));   // 0,7,13,19
    const int ntilesI = (q == 0) ? 7 : 6;
    const int ibase   = itile0 * 4;
    const int iwidth  = ntilesI * 4;

    if (tid < PP) {
        int i0 = pidx[(b * PP + tid) * 2 + 0];
        int i1 = pidx[(b * PP + tid) * 2 + 1];
        float birth = g_filt[i0];
        bs[tid] = birth;
        ps[tid] = g_filt[i1] - birth;
    }
    __syncthreads();

    for (int idx = tid; idx < PP * P_UW; idx += 256) {
        int p = idx / P_UW, t = idx % P_UW;
        float c  = (float)(ibase + t) * 0.01f;
        float db = bs[p] - c;
        Us[idx] = (t < iwidth) ? __expf(-db * db) : 0.f;
    }
    for (int idx = tid; idx < PP * DD; idx += 256) {
        int p = idx / DD, t = idx % DD;
        float c  = (float)t * 0.01f;
        float dp = ps[p] - c;
        Vs[idx] = INV_PI * __expf(-dp * dp);
    }
    __syncthreads();

    const int nt = ntilesI * 25;
    float acc[16];
    float mx = 0.f;
    int i0 = 0, j0 = 0;
    if (tid < nt) {
        i0 = (tid / 25) * 4;
        j0 = (tid % 25) * 4;
        #pragma unroll
        for (int k = 0; k < 16; ++k) acc[k] = 0.f;
        #pragma unroll 4
        for (int p = 0; p < PP; ++p) {
            float4 u = *reinterpret_cast<const float4*>(Us + p * P_UW + i0);
            float4 v = *reinterpret_cast<const float4*>(Vs + p * DD + j0);
            acc[0]  += u.x * v.x; acc[1]  += u.x * v.y; acc[2]  += u.x * v.z; acc[3]  += u.x * v.w;
            acc[4]  += u.y * v.x; acc[5]  += u.y * v.y; acc[6]  += u.y * v.z; acc[7]  += u.y * v.w;
            acc[8]  += u.z * v.x; acc[9]  += u.z * v.y; acc[10] += u.z * v.z; acc[11] += u.z * v.w;
            acc[12] += u.w * v.x; acc[13] += u.w * v.y; acc[14] += u.w * v.z; acc[15] += u.w * v.w;
        }
        #pragma unroll
        for (int k = 0; k < 16; ++k) mx = fmaxf(mx, acc[k]);
    }
    #pragma unroll
    for (int off = 16; off; off >>= 1)
        mx = fmaxf(mx, __shfl_down_sync(0xffffffffu, mx, off));
    if ((tid & 31) == 0) red[tid >> 5] = mx;
    __syncthreads();
    if (tid == 0) {
        float t = red[0];
        #pragma unroll
        for (int w = 1; w < 8; ++w) t = fmaxf(t, red[w]);
        atomicMax(&g_immax[imgch], __float_as_uint(t));
    }

    if (tid < nt) {
        float* outp = g_imgs + imgch * (DD * DD);
        #pragma unroll
        for (int a = 0; a < 4; ++a)
            #pragma unroll
            for (int c = 0; c < 4; ++c)
                outp[(ibase + i0 + a) * DD + (j0 + c)] = acc[a * 4 + c];
    }
}

// ================== tf32 helpers (shared by both TC convs) ==================
__device__ __forceinline__ uint32_t to_tf32(float x) {
    uint32_t r;
    asm("cvt.rna.tf32.f32 %0, %1;" : "=r"(r) : "f"(x));
    return r;
}
__device__ __forceinline__ void mma_tf32(
    float* d, const uint32_t* a, const uint32_t* b)
{
    asm volatile(
        "mma.sync.aligned.m16n8k8.row.col.f32.tf32.tf32.f32 "
        "{%0,%1,%2,%3}, {%4,%5,%6,%7}, {%8,%9}, {%0,%1,%2,%3};\n"
        : "+f"(d[0]), "+f"(d[1]), "+f"(d[2]), "+f"(d[3])
        : "r"(a[0]), "r"(a[1]), "r"(a[2]), "r"(a[3]),
          "r"(b[0]), "r"(b[1]));
}

// ============= K3: conv1 tf32 TC implicit GEMM (+fused normalization) =======
// Per CTA: one image, 5 pooled rows (10 conv rows, M=1000 -> 63 m-tiles),
// N=16 (2 n-tiles), K=50 padded to 56 (7 k-steps). Grid 32x10 = 320 CTAs.
#define C1_TR   14
#define C1_WP   104
#define C1_TILE (2 * C1_TR * C1_WP)            // 2912
#define C1_CS   (1008 * 17)                    // 17136
#define C1_SMEM_FLOATS (C1_CS + 16)            // Cs + bsm (tile/Bf/offs alias Cs)
__global__ __launch_bounds__(256, 2) void conv1_tc_kernel(
    const float* __restrict__ wts, const float* __restrict__ bias)
{
    extern __shared__ float s[];
    float* tile = s;                           // [2][14][104] (mainloop)
    float* Bf   = tile + C1_TILE;              // [7][32][4]
    int*   offs = (int*)(Bf + 7 * 32 * 4);     // [56]
    float* Cs   = s;                           // [1008][17] (post-mainloop)
    float* bsm  = s + C1_CS;                   // [16] survives both phases

    const int img = blockIdx.x;
    const int rg  = blockIdx.y;                // 0..9, 5 pooled rows
    const int tid = threadIdx.x;
    const int lane = tid & 31, warp = tid >> 5;
    const int grp = lane >> 2, qid = lane & 3;

    // B fragments: Bf[ks][lane][2nt+h] = tf32(w[n=g2+8nt][k=8ks+q2+4h]); k>=50 -> 0
    if (tid < 224) {
        const int ks = tid >> 5, ln = tid & 31;
        const int g2 = ln >> 2, q2 = ln & 3;
        float v[4];
        #pragma unroll
        for (int nt = 0; nt < 2; ++nt)
            #pragma unroll
            for (int h = 0; h < 2; ++h) {
                const int k = 8 * ks + q2 + 4 * h;
                v[2 * nt + h] = (k < 50)
                    ? __uint_as_float(to_tf32(wts[(g2 + 8 * nt) * 50 + k])) : 0.f;
            }
        *reinterpret_cast<float4*>(Bf + tid * 4) = *reinterpret_cast<float4*>(v);
    }
    if (tid < 16) bsm[tid] = bias[tid];
    if (tid < 56) {
        const int ic = tid / 25, tap = tid % 25;
        offs[tid] = (tid < 50)
            ? ic * (C1_TR * C1_WP) + (tap / 5) * C1_WP + (tap % 5) : 0;
    }

    const float inv0 = 1.f / __uint_as_float(g_immax[img * 2]);
    const float inv1 = 1.f / __uint_as_float(g_immax[img * 2 + 1]);
    const int iy0 = 10 * rg - 2;
    for (int i = tid; i < C1_TILE; i += 256) {
        const int ic = i / (C1_TR * C1_WP);
        const int r  = (i / C1_WP) % C1_TR;
        const int c  = i % C1_WP;
        const int iy = iy0 + r, ix = c - 2;
        float v = 0.f;
        if (iy >= 0 && iy < 100 && ix >= 0 && ix < 100)
            v = g_imgs[(img * 2 + ic) * (DD * DD) + iy * DD + ix]
                * (ic ? inv1 : inv0);
        tile[i] = __uint_as_float(to_tf32(v));
    }
    __syncthreads();

    // 8 m-tiles per warp: mt = warp + 8t, valid mt<63
    int abase[8][2];
    #pragma unroll
    for (int t = 0; t < 8; ++t) {
        const int mt = warp + 8 * t;
        #pragma unroll
        for (int h = 0; h < 2; ++h) {
            int m = mt * 16 + grp + 8 * h;
            if (m > 999) m = 999;
            abase[t][h] = (m / 100) * C1_WP + (m % 100);
        }
    }

    float acc[8][2][4];
    #pragma unroll
    for (int t = 0; t < 8; ++t)
        #pragma unroll
        for (int nt = 0; nt < 2; ++nt)
            acc[t][nt][0] = acc[t][nt][1] = acc[t][nt][2] = acc[t][nt][3] = 0.f;

    #pragma unroll
    for (int ks = 0; ks < 7; ++ks) {
        const int o0 = offs[ks * 8 + qid];
        const int o1 = offs[ks * 8 + qid + 4];
        const float4 bv = *reinterpret_cast<const float4*>(
            Bf + (ks * 32 + lane) * 4);
        uint32_t b[2][2];
        b[0][0] = __float_as_uint(bv.x); b[0][1] = __float_as_uint(bv.y);
        b[1][0] = __float_as_uint(bv.z); b[1][1] = __float_as_uint(bv.w);

        #pragma unroll
        for (int t = 0; t < 8; ++t) {
            if (warp + 8 * t < 63) {
                uint32_t a[4];
                a[0] = __float_as_uint(tile[abase[t][0] + o0]);
                a[1] = __float_as_uint(tile[abase[t][1] + o0]);
                a[2] = __float_as_uint(tile[abase[t][0] + o1]);
                a[3] = __float_as_uint(tile[abase[t][1] + o1]);
                mma_tf32(acc[t][0], a, b[0]);
                mma_tf32(acc[t][1], a, b[1]);
            }
        }
    }
    __syncthreads();   // tile/Bf dead; Cs takes over

    #pragma unroll
    for (int t = 0; t < 8; ++t) {
        const int mt = warp + 8 * t;
        if (mt < 63) {
            const int m0 = mt * 16 + grp;
            #pragma unroll
            for (int nt = 0; nt < 2; ++nt) {
                const int n0 = nt * 8 + 2 * qid;
                Cs[m0 * 17 + n0]           = acc[t][nt][0];
                Cs[m0 * 17 + n0 + 1]       = acc[t][nt][1];
                Cs[(m0 + 8) * 17 + n0]     = acc[t][nt][2];
                Cs[(m0 + 8) * 17 + n0 + 1] = acc[t][nt][3];
            }
        }
    }
    __syncthreads();

    // fused bias + 2x2 maxpool + relu : 5 pooled rows x 50 x 16 oc = 4000
    for (int idx = tid; idx < 4000; idx += 256) {
        const int oc = idx & 15;
        const int pc = (idx >> 4) % 50;
        const int prl = idx / 800;
        const int prow = 5 * rg + prl;
        const int m00 = 2 * prl * 100 + 2 * pc;
        float v = fmaxf(fmaxf(Cs[m00 * 17 + oc],         Cs[(m00 + 1) * 17 + oc]),
                        fmaxf(Cs[(m00 + 100) * 17 + oc], Cs[(m00 + 101) * 17 + oc]));
        v = fmaxf(v + bsm[oc], 0.f);
        g_y1[((img * 16 + oc) * 50 + prow) * 50 + pc] = v;
    }
}

// ============= K4: conv2 tf32 TC implicit GEMM (R9 proven, ic-major) ========
#define C2_TR   10
#define C2_TILE (16 * C2_TR * 57)                           // 9120
#define C2_SMEM_FLOATS (C2_TILE + 50 * 32 * 8 + 400 + 32)   // 22352
__global__ __launch_bounds__(256, 2) void conv2_tc_kernel(
    const float* __restrict__ wts, const float* __restrict__ bias)
{
    extern __shared__ float s[];
    float* tile = s;                          // [16][10][57]
    float* Bf   = tile + C2_TILE;             // [50][32][8]
    int*   offs = (int*)(Bf + 50 * 32 * 8);   // [400]
    float* bsm  = (float*)(offs + 400);       // [32]
    float* Cs   = s;                          // [304][33] alias (post-mainloop)

    const int img = blockIdx.x;
    const int rg  = blockIdx.y;               // 3-pooled-row group (0..8)
    const int tid = threadIdx.x;
    const int lane = tid & 31, warp = tid >> 5;
    const int grp = lane >> 2, qid = lane & 3;

    for (int idx = tid; idx < 50 * 32; idx += 256) {
        const int ks = idx >> 5, ln = idx & 31;
        const int g2 = ln >> 2, q2 = ln & 3;
        float v[8];
        #pragma unroll
        for (int nt = 0; nt < 4; ++nt) {
            const float* wp = wts + (g2 + 8 * nt) * 400 + 8 * ks + q2;
            v[2 * nt]     = __uint_as_float(to_tf32(wp[0]));
            v[2 * nt + 1] = __uint_as_float(to_tf32(wp[4]));
        }
        float* dst = Bf + idx * 8;
        *reinterpret_cast<float4*>(dst)     = *reinterpret_cast<float4*>(v);
        *reinterpret_cast<float4*>(dst + 4) = *reinterpret_cast<float4*>(v + 4);
    }
    if (tid < 32) bsm[tid] = bias[tid];
    for (int k = tid; k < 400; k += 256) {
        int ic = k / 25, kk = k % 25;
        offs[k] = ic * (C2_TR * 57) + (kk / 5) * 57 + (kk % 5);
    }
    const int iy0 = 6 * rg - 2;
    for (int i = tid; i < C2_TILE; i += 256) {
        int ic = i / (C2_TR * 57), r = (i / 57) % C2_TR, c = i % 57;
        int iy = iy0 + r, ix = c - 2;
        float v = 0.f;
        if (iy >= 0 && iy < 50 && ix >= 0 && ix < 50)
            v = g_y1[((img * 16 + ic) * 50 + iy) * 50 + ix];
        tile[i] = __uint_as_float(to_tf32(v));
    }
    __syncthreads();

    int abase[3][2];
    int nvalid = 0;
    #pragma unroll
    for (int t = 0; t < 3; ++t) {
        const int mt = warp + 8 * t;
        if (mt < 19) nvalid = t + 1;
        #pragma unroll
        for (int h = 0; h < 2; ++h) {
            int m = mt * 16 + grp + h * 8;
            if (m > 299) m = 299;
            abase[t][h] = (m / 50) * 57 + (m % 50);
        }
    }

    float acc[3][4][4];
    #pragma unroll
    for (int t = 0; t < 3; ++t)
        #pragma unroll
        for (int nt = 0; nt < 4; ++nt)
            acc[t][nt][0] = acc[t][nt][1] = acc[t][nt][2] = acc[t][nt][3] = 0.f;

    #pragma unroll 2
    for (int ks = 0; ks < 50; ++ks) {
        const int o0 = offs[ks * 8 + qid];
        const int o1 = offs[ks * 8 + qid + 4];

        const float4* bp = reinterpret_cast<const float4*>(
            Bf + (ks * 32 + lane) * 8);
        float4 bv0 = bp[0], bv1 = bp[1];
        uint32_t b[4][2];
        b[0][0] = __float_as_uint(bv0.x); b[0][1] = __float_as_uint(bv0.y);
        b[1][0] = __float_as_uint(bv0.z); b[1][1] = __float_as_uint(bv0.w);
        b[2][0] = __float_as_uint(bv1.x); b[2][1] = __float_as_uint(bv1.y);
        b[3][0] = __float_as_uint(bv1.z); b[3][1] = __float_as_uint(bv1.w);

        #pragma unroll
        for (int t = 0; t < 3; ++t) {
            if (t < nvalid) {
                uint32_t a[4];
                a[0] = __float_as_uint(tile[abase[t][0] + o0]);
                a[1] = __float_as_uint(tile[abase[t][1] + o0]);
                a[2] = __float_as_uint(tile[abase[t][0] + o1]);
                a[3] = __float_as_uint(tile[abase[t][1] + o1]);
                #pragma unroll
                for (int nt = 0; nt < 4; ++nt)
                    mma_tf32(acc[t][nt], a, b[nt]);
            }
        }
    }

    __syncthreads();

    #pragma unroll
    for (int t = 0; t < 3; ++t) {
        const int mt = warp + 8 * t;
        if (mt < 19) {
            const int m0 = mt * 16 + grp;
            #pragma unroll
            for (int nt = 0; nt < 4; ++nt) {
                const int n0 = nt * 8 + 2 * qid;
                Cs[m0 * 33 + n0]           = acc[t][nt][0];
                Cs[m0 * 33 + n0 + 1]       = acc[t][nt][1];
                Cs[(m0 + 8) * 33 + n0]     = acc[t][nt][2];
                Cs[(m0 + 8) * 33 + n0 + 1] = acc[t][nt][3];
            }
        }
    }
    __syncthreads();

    for (int idx = tid; idx < 2400; idx += 256) {
        const int oc = idx & 31;
        const int pc = (idx >> 5) % 25;
        const int prl = idx / 800;
        const int prow = 3 * rg + prl;
        if (prow < 25) {
            const int m00 = 2 * prl * 50 + 2 * pc;
            float v = fmaxf(fmaxf(Cs[m00 * 33 + oc],        Cs[(m00 + 1) * 33 + oc]),
                            fmaxf(Cs[(m00 + 50) * 33 + oc], Cs[(m00 + 51) * 33 + oc]));
            v = fmaxf(v + bsm[oc], 0.f);
            g_y2[((img * 32 + oc) * 25 + prow) * 25 + pc] = v;
        }
    }
}

// ======================= K5: FC head ========================================
__global__ __launch_bounds__(256) void fc_kernel(
    const float* __restrict__ w, const float* __restrict__ b,
    float* __restrict__ out)
{
    const int bc = blockIdx.x;
    const int bi = bc / NCLS, c = bc % NCLS;
    const float4* yb = reinterpret_cast<const float4*>(g_y2 + bi * 20000);
    const float4* wc = reinterpret_cast<const float4*>(w + c * 20000);
    float s = 0.f;
    for (int k = threadIdx.x; k < 5000; k += 256) {
        float4 a = yb[k], ww = wc[k];
        s += a.x * ww.x + a.y * ww.y + a.z * ww.z + a.w * ww.w;
    }
    #pragma unroll
    for (int off = 16; off; off >>= 1)
        s += __shfl_down_sync(0xffffffffu, s, off);
    __shared__ float red[8];
    if ((threadIdx.x & 31) == 0) red[threadIdx.x >> 5] = s;
    __syncthreads();
    if (threadIdx.x == 0) {
        float t = 0.f;
        #pragma unroll
        for (int wi = 0; wi < 8; ++wi) t += red[wi];
        out[bi * NCLS + c] = t + b[c];
    }
}

// ============================== launch ======================================
extern "C" void kernel_launch(void* const* d_in, const int* in_sizes, int n_in,
                              void* d_out, int out_size)
{
    const float* x        = (const float*)d_in[0];
    const int*   pidx0    = (const int*)  d_in[1];
    const int*   pidx1    = (const int*)  d_in[2];
    const float* w1       = (const float*)d_in[3];
    const float* b1       = (const float*)d_in[4];
    const float* w2       = (const float*)d_in[5];
    const float* b2       = (const float*)d_in[6];
    const float* conv1_w  = (const float*)d_in[7];
    const float* conv1_b  = (const float*)d_in[8];
    const float* conv2_w  = (const float*)d_in[9];
    const float* conv2_b  = (const float*)d_in[10];
    const float* out_w    = (const float*)d_in[11];
    const float* out_b    = (const float*)d_in[12];
    float* out = (float*)d_out;

    const int pers_smem  = PERS_SMEM_FLOATS * 4;   // 66816
    const int conv1_smem = C1_SMEM_FLOATS * 4;     // 68608
    const int conv2_smem = C2_SMEM_FLOATS * 4;     // 89408

    cudaFuncSetAttribute(pers_image_kernel,
        cudaFuncAttributeMaxDynamicSharedMemorySize, pers_smem);
    cudaFuncSetAttribute(conv1_tc_kernel,
        cudaFuncAttributeMaxDynamicSharedMemorySize, conv1_smem);
    cudaFuncSetAttribute(conv2_tc_kernel,
        cudaFuncAttributeMaxDynamicSharedMemorySize, conv2_smem);

    // K1: node filtration -> g_filt and d_out[320:]  (also resets g_immax)
    filt_kernel<<<250, 256>>>(x, w1, b1, w2, b2, out + BB * NCLS);

    // K2: persistence images (unnormalized) + per-imgch max, 256 blocks
    pers_image_kernel<<<256, 256, pers_smem>>>(pidx0, pidx1);

    // K3: conv1 via tf32 TC (+fused normalization) -> g_y1
    conv1_tc_kernel<<<dim3(32, 10), 256, conv1_smem>>>(conv1_w, conv1_b);

    // K4: conv2 via tf32 TC, one balanced wave (288 CTAs) -> g_y2
    conv2_tc_kernel<<<dim3(32, 9), 256, conv2_smem>>>(conv2_w, conv2_b);

    // K5: FC -> d_out[0:320]
    fc_kernel<<<BB * NCLS, 256>>>(out_w, out_b, out);
}